// round 1
// baseline (speedup 1.0000x reference)
#include <cuda_runtime.h>
#include <math.h>

#define NTOK 8192      // B * L = 4 * 2048
#define DMODEL 512
#define NHEAD 8
#define HDIM 64
#define FDIM 2048
#define NEXP 4
#define SEQ 2048

// ---------------- scratch (device globals; no allocation allowed) ----------
__device__ float g_qkv[(size_t)NTOK * 1536];   // SA qkv / CA q + kv (reused)
__device__ float g_attn[(size_t)NTOK * DMODEL];
__device__ float g_tmp[(size_t)NTOK * DMODEL];
__device__ float g_x1[(size_t)NTOK * DMODEL];
__device__ float g_x2[(size_t)NTOK * DMODEL];
__device__ float g_h[(size_t)NTOK * FDIM];
__device__ int   g_cnt[NEXP];
__device__ int   g_list[NEXP * NTOK];

__global__ void zero_cnt_kernel() {
    if (threadIdx.x < NEXP) g_cnt[threadIdx.x] = 0;
}

// ---------------- GEMM: C[M,N] = A[M,K] @ B[N,K]^T + bias (+ resid) --------
// tiles 128x64x16, 256 threads, 8x4 micro-tile per thread
__global__ void __launch_bounds__(256) gemm_nt(
    const float* __restrict__ A, const float* __restrict__ Bw,
    const float* __restrict__ bias, const float* __restrict__ resid,
    float* __restrict__ C, int M, int N, int K)
{
    __shared__ float As[16][128];
    __shared__ float Bs[16][64];
    const int t = threadIdx.x;
    const int tx = t & 15, ty = t >> 4;
    const int row0 = blockIdx.y * 128;
    const int col0 = blockIdx.x * 64;
    float acc[8][4] = {};
    for (int k0 = 0; k0 < K; k0 += 16) {
#pragma unroll
        for (int p = 0; p < 2; ++p) {
            int idx = t + p * 256;
            int m = idx >> 2, kc = (idx & 3) << 2;
            float4 v = *reinterpret_cast<const float4*>(&A[(size_t)(row0 + m) * K + k0 + kc]);
            As[kc + 0][m] = v.x; As[kc + 1][m] = v.y;
            As[kc + 2][m] = v.z; As[kc + 3][m] = v.w;
        }
        {
            int n = t >> 2, kc = (t & 3) << 2;
            float4 v = *reinterpret_cast<const float4*>(&Bw[(size_t)(col0 + n) * K + k0 + kc]);
            Bs[kc + 0][n] = v.x; Bs[kc + 1][n] = v.y;
            Bs[kc + 2][n] = v.z; Bs[kc + 3][n] = v.w;
        }
        __syncthreads();
#pragma unroll
        for (int k = 0; k < 16; ++k) {
            float4 a0 = *reinterpret_cast<const float4*>(&As[k][ty * 8]);
            float4 a1 = *reinterpret_cast<const float4*>(&As[k][ty * 8 + 4]);
            float4 b  = *reinterpret_cast<const float4*>(&Bs[k][tx * 4]);
            float av[8] = {a0.x, a0.y, a0.z, a0.w, a1.x, a1.y, a1.z, a1.w};
            float bv[4] = {b.x, b.y, b.z, b.w};
#pragma unroll
            for (int i = 0; i < 8; ++i)
#pragma unroll
                for (int j = 0; j < 4; ++j)
                    acc[i][j] = fmaf(av[i], bv[j], acc[i][j]);
        }
        __syncthreads();
    }
    float4 b4 = *reinterpret_cast<const float4*>(&bias[col0 + tx * 4]);
#pragma unroll
    for (int i = 0; i < 8; ++i) {
        int r = row0 + ty * 8 + i;
        float4 o = make_float4(acc[i][0] + b4.x, acc[i][1] + b4.y,
                               acc[i][2] + b4.z, acc[i][3] + b4.w);
        if (resid) {
            float4 rr = *reinterpret_cast<const float4*>(&resid[(size_t)r * N + col0 + tx * 4]);
            o.x += rr.x; o.y += rr.y; o.z += rr.z; o.w += rr.w;
        }
        *reinterpret_cast<float4*>(&C[(size_t)r * N + col0 + tx * 4]) = o;
    }
}

// ---------------- MoE grouped GEMM (gathered rows), B is [K,N] -------------
// Y[tok,:] = act(X[tok,:] @ W[e] + b[e]) (+ resid[tok,:])
template<bool GELU, bool RESID>
__global__ void __launch_bounds__(256) gemm_moe(
    const float* __restrict__ X, const float* __restrict__ W,
    const float* __restrict__ bias, const float* __restrict__ resid,
    float* __restrict__ Y, int K, int N)
{
    const int e = blockIdx.y >> 6;          // 64 row-tiles max per expert
    const int tile = blockIdx.y & 63;
    const int cnt = g_cnt[e];
    if (tile * 128 >= cnt) return;
    __shared__ float As[16][128];
    __shared__ float Bs[16][64];
    __shared__ int rows[128];
    const int t = threadIdx.x;
    if (t < 128) {
        int gi = tile * 128 + t;
        rows[t] = (gi < cnt) ? g_list[e * NTOK + gi] : -1;
    }
    __syncthreads();
    const int tx = t & 15, ty = t >> 4;
    const int col0 = blockIdx.x * 64;
    const float* We = W + (size_t)e * K * N;
    float acc[8][4] = {};
    for (int k0 = 0; k0 < K; k0 += 16) {
#pragma unroll
        for (int p = 0; p < 2; ++p) {
            int idx = t + p * 256;
            int m = idx >> 2, kc = (idx & 3) << 2;
            int r = rows[m];
            float4 v = make_float4(0.f, 0.f, 0.f, 0.f);
            if (r >= 0)
                v = *reinterpret_cast<const float4*>(&X[(size_t)r * K + k0 + kc]);
            As[kc + 0][m] = v.x; As[kc + 1][m] = v.y;
            As[kc + 2][m] = v.z; As[kc + 3][m] = v.w;
        }
        {
            int kk = t >> 4, n4 = (t & 15) << 2;
            float4 v = *reinterpret_cast<const float4*>(&We[(size_t)(k0 + kk) * N + col0 + n4]);
            *reinterpret_cast<float4*>(&Bs[kk][n4]) = v;
        }
        __syncthreads();
#pragma unroll
        for (int k = 0; k < 16; ++k) {
            float4 a0 = *reinterpret_cast<const float4*>(&As[k][ty * 8]);
            float4 a1 = *reinterpret_cast<const float4*>(&As[k][ty * 8 + 4]);
            float4 b  = *reinterpret_cast<const float4*>(&Bs[k][tx * 4]);
            float av[8] = {a0.x, a0.y, a0.z, a0.w, a1.x, a1.y, a1.z, a1.w};
            float bv[4] = {b.x, b.y, b.z, b.w};
#pragma unroll
            for (int i = 0; i < 8; ++i)
#pragma unroll
                for (int j = 0; j < 4; ++j)
                    acc[i][j] = fmaf(av[i], bv[j], acc[i][j]);
        }
        __syncthreads();
    }
    float4 b4 = *reinterpret_cast<const float4*>(&bias[(size_t)e * N + col0 + tx * 4]);
#pragma unroll
    for (int i = 0; i < 8; ++i) {
        int m = ty * 8 + i;
        int tok = rows[m];
        if (tok < 0) continue;
        float v[4] = {acc[i][0] + b4.x, acc[i][1] + b4.y,
                      acc[i][2] + b4.z, acc[i][3] + b4.w};
        if (GELU) {
#pragma unroll
            for (int j = 0; j < 4; ++j)
                v[j] = 0.5f * v[j] * (1.f + erff(v[j] * 0.70710678118654752f));
        }
        if (RESID) {
            float4 rr = *reinterpret_cast<const float4*>(&resid[(size_t)tok * N + col0 + tx * 4]);
            v[0] += rr.x; v[1] += rr.y; v[2] += rr.z; v[3] += rr.w;
        }
        float4 o = make_float4(v[0], v[1], v[2], v[3]);
        *reinterpret_cast<float4*>(&Y[(size_t)tok * N + col0 + tx * 4]) = o;
    }
}

// ---------------- flash attention, fp32, 64-query tiles --------------------
// q at qb[row*qs + h*64 + d]; k/v analogous. out[row*512 + h*64 + d].
__global__ void __launch_bounds__(256) flash_attn(
    const float* __restrict__ qb, int qs,
    const float* __restrict__ kb, int ks,
    const float* __restrict__ vb, int vs,
    float* __restrict__ out, int Lk)
{
    __shared__ float Qs[64 * 64];   // [d][row]
    __shared__ float KVs[64 * 64];  // K: [d][key], then V: [key][col]
    __shared__ float Ps[64 * 64];   // [key][row], XOR-swizzled at float4 grain
    const int t = threadIdx.x;
    const int tx = t & 15, ty = t >> 4;
    const int b = blockIdx.x >> 3;
    const int h = blockIdx.x & 7;
    const int q0 = b * SEQ + blockIdx.y * 64;
    const int kbase = b * Lk;
    const int hoff = h * HDIM;
    {
        int r = t >> 2;
        int dc = (t & 3) << 2;
#pragma unroll
        for (int pass = 0; pass < 4; ++pass) {
            int d0 = dc + pass * 16;
            float4 v = *reinterpret_cast<const float4*>(&qb[(size_t)(q0 + r) * qs + hoff + d0]);
            Qs[(d0 + 0) * 64 + r] = v.x * 0.125f;
            Qs[(d0 + 1) * 64 + r] = v.y * 0.125f;
            Qs[(d0 + 2) * 64 + r] = v.z * 0.125f;
            Qs[(d0 + 3) * 64 + r] = v.w * 0.125f;
        }
    }
    float m_i[4], l_i[4], acc[4][4] = {};
#pragma unroll
    for (int i = 0; i < 4; ++i) { m_i[i] = -1e30f; l_i[i] = 0.f; }

    for (int kt = 0; kt < Lk; kt += 64) {
        __syncthreads();   // prior O-gemm done with KVs & Ps
        {
            int r = t >> 2;
            int dc = (t & 3) << 2;
#pragma unroll
            for (int pass = 0; pass < 4; ++pass) {
                int d0 = dc + pass * 16;
                float4 v = *reinterpret_cast<const float4*>(&kb[(size_t)(kbase + kt + r) * ks + hoff + d0]);
                KVs[(d0 + 0) * 64 + r] = v.x;
                KVs[(d0 + 1) * 64 + r] = v.y;
                KVs[(d0 + 2) * 64 + r] = v.z;
                KVs[(d0 + 3) * 64 + r] = v.w;
            }
        }
        __syncthreads();
        float s[4][4] = {};
#pragma unroll
        for (int d = 0; d < 64; ++d) {
            float4 a  = *reinterpret_cast<const float4*>(&Qs[d * 64 + ty * 4]);
            float4 bk = *reinterpret_cast<const float4*>(&KVs[d * 64 + tx * 4]);
            float av[4] = {a.x, a.y, a.z, a.w};
            float bv[4] = {bk.x, bk.y, bk.z, bk.w};
#pragma unroll
            for (int i = 0; i < 4; ++i)
#pragma unroll
                for (int j = 0; j < 4; ++j)
                    s[i][j] = fmaf(av[i], bv[j], s[i][j]);
        }
        // online softmax (reduction over the 16-lane tx group; same ty per group)
#pragma unroll
        for (int i = 0; i < 4; ++i) {
            float mt = fmaxf(fmaxf(s[i][0], s[i][1]), fmaxf(s[i][2], s[i][3]));
#pragma unroll
            for (int off = 8; off >= 1; off >>= 1)
                mt = fmaxf(mt, __shfl_xor_sync(0xffffffffu, mt, off));
            float mn = fmaxf(m_i[i], mt);
            float alpha = __expf(m_i[i] - mn);
            m_i[i] = mn;
            float rs = 0.f;
#pragma unroll
            for (int j = 0; j < 4; ++j) { s[i][j] = __expf(s[i][j] - mn); rs += s[i][j]; }
#pragma unroll
            for (int off = 8; off >= 1; off >>= 1)
                rs += __shfl_xor_sync(0xffffffffu, rs, off);
            l_i[i] = l_i[i] * alpha + rs;
#pragma unroll
            for (int j = 0; j < 4; ++j) acc[i][j] *= alpha;
        }
        __syncthreads();   // done reading K from KVs
        // store P (swizzled), load V
#pragma unroll
        for (int j = 0; j < 4; ++j) {
            int k = tx * 4 + j;
            int base = k * 64 + ((ty ^ (k & 15)) << 2);
#pragma unroll
            for (int i = 0; i < 4; ++i) Ps[base + i] = s[i][j];
        }
        {
            int r = t >> 4;
            int c0 = (t & 15) << 2;
#pragma unroll
            for (int pass = 0; pass < 4; ++pass) {
                int rr = r + pass * 16;
                float4 v = *reinterpret_cast<const float4*>(&vb[(size_t)(kbase + kt + rr) * vs + hoff + c0]);
                *reinterpret_cast<float4*>(&KVs[rr * 64 + c0]) = v;
            }
        }
        __syncthreads();
#pragma unroll
        for (int k = 0; k < 64; ++k) {
            float4 p = *reinterpret_cast<const float4*>(&Ps[k * 64 + ((ty ^ (k & 15)) << 2)]);
            float4 v = *reinterpret_cast<const float4*>(&KVs[k * 64 + tx * 4]);
            float pv[4] = {p.x, p.y, p.z, p.w};
            float vv[4] = {v.x, v.y, v.z, v.w};
#pragma unroll
            for (int i = 0; i < 4; ++i)
#pragma unroll
                for (int j = 0; j < 4; ++j)
                    acc[i][j] = fmaf(pv[i], vv[j], acc[i][j]);
        }
    }
#pragma unroll
    for (int i = 0; i < 4; ++i) {
        float inv = 1.f / l_i[i];
        int r = q0 + ty * 4 + i;
        float4 o = make_float4(acc[i][0] * inv, acc[i][1] * inv,
                               acc[i][2] * inv, acc[i][3] * inv);
        *reinterpret_cast<float4*>(&out[(size_t)r * DMODEL + hoff + tx * 4]) = o;
    }
}

// ---------------- LayerNorm over D=512 -------------------------------------
__global__ void __launch_bounds__(128) layernorm_k(
    const float* __restrict__ in, const float* __restrict__ g,
    const float* __restrict__ bt, float* __restrict__ out)
{
    const int row = blockIdx.x;
    const int t = threadIdx.x;
    float4 v = *reinterpret_cast<const float4*>(&in[(size_t)row * 512 + t * 4]);
    float s  = v.x + v.y + v.z + v.w;
    float s2 = v.x * v.x + v.y * v.y + v.z * v.z + v.w * v.w;
#pragma unroll
    for (int off = 16; off >= 1; off >>= 1) {
        s  += __shfl_xor_sync(0xffffffffu, s,  off);
        s2 += __shfl_xor_sync(0xffffffffu, s2, off);
    }
    __shared__ float sh[8];
    int w = t >> 5;
    if ((t & 31) == 0) { sh[w] = s; sh[w + 4] = s2; }
    __syncthreads();
    float ts  = sh[0] + sh[1] + sh[2] + sh[3];
    float ts2 = sh[4] + sh[5] + sh[6] + sh[7];
    float mu  = ts * (1.f / 512.f);
    float var = ts2 * (1.f / 512.f) - mu * mu;
    float inv = rsqrtf(var + 1e-5f);
    float4 gg = *reinterpret_cast<const float4*>(&g[t * 4]);
    float4 bb = *reinterpret_cast<const float4*>(&bt[t * 4]);
    float4 o;
    o.x = (v.x - mu) * inv * gg.x + bb.x;
    o.y = (v.y - mu) * inv * gg.y + bb.y;
    o.z = (v.z - mu) * inv * gg.z + bb.z;
    o.w = (v.w - mu) * inv * gg.w + bb.w;
    *reinterpret_cast<float4*>(&out[(size_t)row * 512 + t * 4]) = o;
}

// ---------------- gate: top-1 routing (argmax of logits) -------------------
__global__ void __launch_bounds__(256) gate_k(
    const float* __restrict__ x, const float* __restrict__ gw,
    const float* __restrict__ gb)
{
    int warp = threadIdx.x >> 5, lane = threadIdx.x & 31;
    int tok = blockIdx.x * 8 + warp;
    float s0 = 0, s1 = 0, s2 = 0, s3 = 0;
    const float* xr = &x[(size_t)tok * 512];
#pragma unroll
    for (int d = lane * 4; d < 512; d += 128) {
        float4 xv = *reinterpret_cast<const float4*>(&xr[d]);
        float4 w0 = *reinterpret_cast<const float4*>(&gw[d]);
        float4 w1 = *reinterpret_cast<const float4*>(&gw[512 + d]);
        float4 w2 = *reinterpret_cast<const float4*>(&gw[1024 + d]);
        float4 w3 = *reinterpret_cast<const float4*>(&gw[1536 + d]);
        s0 += xv.x * w0.x + xv.y * w0.y + xv.z * w0.z + xv.w * w0.w;
        s1 += xv.x * w1.x + xv.y * w1.y + xv.z * w1.z + xv.w * w1.w;
        s2 += xv.x * w2.x + xv.y * w2.y + xv.z * w2.z + xv.w * w2.w;
        s3 += xv.x * w3.x + xv.y * w3.y + xv.z * w3.z + xv.w * w3.w;
    }
#pragma unroll
    for (int off = 16; off >= 1; off >>= 1) {
        s0 += __shfl_xor_sync(0xffffffffu, s0, off);
        s1 += __shfl_xor_sync(0xffffffffu, s1, off);
        s2 += __shfl_xor_sync(0xffffffffu, s2, off);
        s3 += __shfl_xor_sync(0xffffffffu, s3, off);
    }
    if (lane == 0) {
        s0 += gb[0]; s1 += gb[1]; s2 += gb[2]; s3 += gb[3];
        int best = 0; float bv = s0;
        if (s1 > bv) { bv = s1; best = 1; }
        if (s2 > bv) { bv = s2; best = 2; }
        if (s3 > bv) { bv = s3; best = 3; }
        int pos = atomicAdd(&g_cnt[best], 1);
        g_list[best * NTOK + pos] = tok;
    }
}

// ---------------- launch ----------------------------------------------------
extern "C" void kernel_launch(void* const* d_in, const int* in_sizes, int n_in,
                              void* d_out, int out_size)
{
    const float* x        = (const float*)d_in[0];
    const float* memory   = (const float*)d_in[1];
    const float* sa_in_w  = (const float*)d_in[2];
    const float* sa_in_b  = (const float*)d_in[3];
    const float* sa_out_w = (const float*)d_in[4];
    const float* sa_out_b = (const float*)d_in[5];
    const float* ca_in_w  = (const float*)d_in[6];
    const float* ca_in_b  = (const float*)d_in[7];
    const float* ca_out_w = (const float*)d_in[8];
    const float* ca_out_b = (const float*)d_in[9];
    const float* gate_w   = (const float*)d_in[10];
    const float* gate_b   = (const float*)d_in[11];
    const float* w1       = (const float*)d_in[12];
    const float* b1       = (const float*)d_in[13];
    const float* w2       = (const float*)d_in[14];
    const float* b2       = (const float*)d_in[15];
    const float* ln1_g    = (const float*)d_in[16];
    const float* ln1_b    = (const float*)d_in[17];
    const float* ln2_g    = (const float*)d_in[18];
    const float* ln2_b    = (const float*)d_in[19];
    const float* ln3_g    = (const float*)d_in[20];
    const float* ln3_b    = (const float*)d_in[21];
    float* out = (float*)d_out;

    float *qkv, *attn, *tmp, *x1, *x2, *hbuf;
    cudaGetSymbolAddress((void**)&qkv,  g_qkv);
    cudaGetSymbolAddress((void**)&attn, g_attn);
    cudaGetSymbolAddress((void**)&tmp,  g_tmp);
    cudaGetSymbolAddress((void**)&x1,   g_x1);
    cudaGetSymbolAddress((void**)&x2,   g_x2);
    cudaGetSymbolAddress((void**)&hbuf, g_h);

    zero_cnt_kernel<<<1, 32>>>();

    // --- self-attention ---
    gemm_nt<<<dim3(24, 64), 256>>>(x, sa_in_w, sa_in_b, nullptr, qkv, NTOK, 1536, 512);
    flash_attn<<<dim3(32, 32), 256>>>(qkv, 1536, qkv + 512, 1536, qkv + 1024, 1536, attn, SEQ);
    gemm_nt<<<dim3(8, 64), 256>>>(attn, sa_out_w, sa_out_b, x, tmp, NTOK, 512, 512);
    layernorm_k<<<NTOK, 128>>>(tmp, ln1_g, ln1_b, x1);

    // --- cross-attention ---
    gemm_nt<<<dim3(8, 64), 256>>>(x1, ca_in_w, ca_in_b, nullptr, qkv, NTOK, 512, 512);
    gemm_nt<<<dim3(16, 64), 256>>>(memory, ca_in_w + 512 * 512, ca_in_b + 512, nullptr,
                                   qkv + (size_t)NTOK * 512, NTOK, 1024, 512);
    flash_attn<<<dim3(32, 32), 256>>>(qkv, 512,
                                      qkv + (size_t)NTOK * 512, 1024,
                                      qkv + (size_t)NTOK * 512 + 512, 1024, attn, SEQ);
    gemm_nt<<<dim3(8, 64), 256>>>(attn, ca_out_w, ca_out_b, x1, tmp, NTOK, 512, 512);
    layernorm_k<<<NTOK, 128>>>(tmp, ln2_g, ln2_b, x2);

    // --- MoE FFN (top-1 routed; only the selected expert is computed) ---
    gate_k<<<NTOK / 8, 256>>>(x2, gate_w, gate_b);
    gemm_moe<true,  false><<<dim3(32, 256), 256>>>(x2,   w1, b1, nullptr, hbuf, 512, 2048);
    gemm_moe<false, true ><<<dim3(8,  256), 256>>>(hbuf, w2, b2, x2,      tmp,  2048, 512);
    layernorm_k<<<NTOK, 128>>>(tmp, ln3_g, ln3_b, out);
}

// round 2
// speedup vs baseline: 2.7845x; 2.7845x over previous
#include <cuda_runtime.h>
#include <math.h>
#include <stdint.h>

#define NTOK 8192      // B * L = 4 * 2048
#define DMODEL 512
#define HDIM 64
#define FDIM 2048
#define NEXP 4
#define SEQ 2048

// ---------------- scratch (device globals; no allocation allowed) ----------
__device__ float g_qkv[(size_t)NTOK * 1536];
__device__ float g_attn[(size_t)NTOK * DMODEL];
__device__ float g_tmp[(size_t)NTOK * DMODEL];
__device__ float g_x1[(size_t)NTOK * DMODEL];
__device__ float g_x2[(size_t)NTOK * DMODEL];
__device__ float g_h[(size_t)NTOK * FDIM];
__device__ int   g_cnt[NEXP];
__device__ int   g_list[NEXP * NTOK];

__global__ void zero_cnt_kernel() {
    if (threadIdx.x < NEXP) g_cnt[threadIdx.x] = 0;
}

// ---------------- tf32 helpers ---------------------------------------------
__device__ __forceinline__ uint32_t f2tf(float f) {
    uint32_t u;
    asm("cvt.rna.tf32.f32 %0, %1;" : "=r"(u) : "f"(f));
    return u;
}

__device__ __forceinline__ void mma8(float* c, uint32_t a0, uint32_t a1,
                                     uint32_t a2, uint32_t a3,
                                     uint32_t b0, uint32_t b1) {
    asm volatile(
        "mma.sync.aligned.m16n8k8.row.col.f32.tf32.tf32.f32 "
        "{%0,%1,%2,%3},{%4,%5,%6,%7},{%8,%9},{%0,%1,%2,%3};"
        : "+f"(c[0]), "+f"(c[1]), "+f"(c[2]), "+f"(c[3])
        : "r"(a0), "r"(a1), "r"(a2), "r"(a3), "r"(b0), "r"(b1));
}

// ---------------- GEMM: C[M,N] = A[M,K] @ B[N,K]^T + bias (+resid) ---------
// 128x64x32 tile, 8 warps (4x2), warp tile 32x32, tf32 mma
__global__ void __launch_bounds__(256) gemm_nt(
    const float* __restrict__ A, const float* __restrict__ Bw,
    const float* __restrict__ bias, const float* __restrict__ resid,
    float* __restrict__ C, int M, int N, int K)
{
    __shared__ uint32_t As[128][36];
    __shared__ uint32_t Bs[64][36];
    const int t = threadIdx.x;
    const int lane = t & 31, wid = t >> 5;
    const int gid = lane >> 2, tig = lane & 3;
    const int wm = (wid & 3) * 32, wn = (wid >> 2) * 32;
    const int row0 = blockIdx.y * 128, col0 = blockIdx.x * 64;
    const int lr = t >> 3, lc = (t & 7) * 4;

    float4 ra[4], rb[2];
#pragma unroll
    for (int p = 0; p < 4; ++p)
        ra[p] = *(const float4*)&A[(size_t)(row0 + lr + p * 32) * K + lc];
#pragma unroll
    for (int p = 0; p < 2; ++p)
        rb[p] = *(const float4*)&Bw[(size_t)(col0 + lr + p * 32) * K + lc];
#pragma unroll
    for (int p = 0; p < 4; ++p) {
        uint32_t* d = &As[lr + p * 32][lc];
        d[0] = f2tf(ra[p].x); d[1] = f2tf(ra[p].y);
        d[2] = f2tf(ra[p].z); d[3] = f2tf(ra[p].w);
    }
#pragma unroll
    for (int p = 0; p < 2; ++p) {
        uint32_t* d = &Bs[lr + p * 32][lc];
        d[0] = f2tf(rb[p].x); d[1] = f2tf(rb[p].y);
        d[2] = f2tf(rb[p].z); d[3] = f2tf(rb[p].w);
    }
    __syncthreads();

    float acc[2][4][4] = {};
    for (int k0 = 0; k0 < K; k0 += 32) {
        const bool more = (k0 + 32) < K;
        if (more) {
#pragma unroll
            for (int p = 0; p < 4; ++p)
                ra[p] = *(const float4*)&A[(size_t)(row0 + lr + p * 32) * K + k0 + 32 + lc];
#pragma unroll
            for (int p = 0; p < 2; ++p)
                rb[p] = *(const float4*)&Bw[(size_t)(col0 + lr + p * 32) * K + k0 + 32 + lc];
        }
#pragma unroll
        for (int s = 0; s < 4; ++s) {
            const int ks = s * 8;
            uint32_t a[2][4], b[4][2];
#pragma unroll
            for (int i = 0; i < 2; ++i) {
                a[i][0] = As[wm + i * 16 + gid][ks + tig];
                a[i][1] = As[wm + i * 16 + gid + 8][ks + tig];
                a[i][2] = As[wm + i * 16 + gid][ks + tig + 4];
                a[i][3] = As[wm + i * 16 + gid + 8][ks + tig + 4];
            }
#pragma unroll
            for (int j = 0; j < 4; ++j) {
                b[j][0] = Bs[wn + j * 8 + gid][ks + tig];
                b[j][1] = Bs[wn + j * 8 + gid][ks + tig + 4];
            }
#pragma unroll
            for (int i = 0; i < 2; ++i)
#pragma unroll
                for (int j = 0; j < 4; ++j)
                    mma8(acc[i][j], a[i][0], a[i][1], a[i][2], a[i][3], b[j][0], b[j][1]);
        }
        if (more) {
            __syncthreads();
#pragma unroll
            for (int p = 0; p < 4; ++p) {
                uint32_t* d = &As[lr + p * 32][lc];
                d[0] = f2tf(ra[p].x); d[1] = f2tf(ra[p].y);
                d[2] = f2tf(ra[p].z); d[3] = f2tf(ra[p].w);
            }
#pragma unroll
            for (int p = 0; p < 2; ++p) {
                uint32_t* d = &Bs[lr + p * 32][lc];
                d[0] = f2tf(rb[p].x); d[1] = f2tf(rb[p].y);
                d[2] = f2tf(rb[p].z); d[3] = f2tf(rb[p].w);
            }
            __syncthreads();
        }
    }

#pragma unroll
    for (int j = 0; j < 4; ++j) {
        const int c = col0 + wn + j * 8 + 2 * tig;
        float2 bj = *(const float2*)&bias[c];
#pragma unroll
        for (int i = 0; i < 2; ++i) {
            const int r0 = row0 + wm + i * 16 + gid;
            float2 v0 = make_float2(acc[i][j][0] + bj.x, acc[i][j][1] + bj.y);
            float2 v1 = make_float2(acc[i][j][2] + bj.x, acc[i][j][3] + bj.y);
            if (resid) {
                float2 q0 = *(const float2*)&resid[(size_t)r0 * N + c];
                float2 q1 = *(const float2*)&resid[(size_t)(r0 + 8) * N + c];
                v0.x += q0.x; v0.y += q0.y; v1.x += q1.x; v1.y += q1.y;
            }
            *(float2*)&C[(size_t)r0 * N + c] = v0;
            *(float2*)&C[(size_t)(r0 + 8) * N + c] = v1;
        }
    }
}

// ---------------- MoE grouped GEMM (gather rows), W is [E][K][N] ------------
template<bool GELU, bool RESID>
__global__ void __launch_bounds__(256) gemm_moe(
    const float* __restrict__ X, const float* __restrict__ W,
    const float* __restrict__ bias, const float* __restrict__ resid,
    float* __restrict__ Y, int K, int N)
{
    const int e = blockIdx.y >> 6;
    const int tile = blockIdx.y & 63;
    const int cnt = g_cnt[e];
    if (tile * 128 >= cnt) return;

    __shared__ uint32_t As[128][36];
    __shared__ uint32_t Bs[32][72];
    __shared__ int rows[128];
    const int t = threadIdx.x;
    if (t < 128) {
        int gi = tile * 128 + t;
        rows[t] = (gi < cnt) ? g_list[e * NTOK + gi] : -1;
    }
    __syncthreads();

    const int lane = t & 31, wid = t >> 5;
    const int gid = lane >> 2, tig = lane & 3;
    const int wm = (wid & 3) * 32, wn = (wid >> 2) * 32;
    const int col0 = blockIdx.x * 64;
    const float* We = W + (size_t)e * K * N;

    const int lr = t >> 3, lc = (t & 7) * 4;       // A tile mapping
    const int bk = t >> 4, bn = (t & 15) * 4;      // B tile mapping

    float4 ra[4], rb[2];
#pragma unroll
    for (int p = 0; p < 4; ++p) {
        int r = rows[lr + p * 32];
        ra[p] = (r >= 0) ? *(const float4*)&X[(size_t)r * K + lc]
                         : make_float4(0.f, 0.f, 0.f, 0.f);
    }
#pragma unroll
    for (int p = 0; p < 2; ++p)
        rb[p] = *(const float4*)&We[(size_t)(bk + p * 16) * N + col0 + bn];
#pragma unroll
    for (int p = 0; p < 4; ++p) {
        uint32_t* d = &As[lr + p * 32][lc];
        d[0] = f2tf(ra[p].x); d[1] = f2tf(ra[p].y);
        d[2] = f2tf(ra[p].z); d[3] = f2tf(ra[p].w);
    }
#pragma unroll
    for (int p = 0; p < 2; ++p) {
        uint32_t* d = &Bs[bk + p * 16][bn];
        d[0] = f2tf(rb[p].x); d[1] = f2tf(rb[p].y);
        d[2] = f2tf(rb[p].z); d[3] = f2tf(rb[p].w);
    }
    __syncthreads();

    float acc[2][4][4] = {};
    for (int k0 = 0; k0 < K; k0 += 32) {
        const bool more = (k0 + 32) < K;
        if (more) {
#pragma unroll
            for (int p = 0; p < 4; ++p) {
                int r = rows[lr + p * 32];
                ra[p] = (r >= 0) ? *(const float4*)&X[(size_t)r * K + k0 + 32 + lc]
                                 : make_float4(0.f, 0.f, 0.f, 0.f);
            }
#pragma unroll
            for (int p = 0; p < 2; ++p)
                rb[p] = *(const float4*)&We[(size_t)(k0 + 32 + bk + p * 16) * N + col0 + bn];
        }
#pragma unroll
        for (int s = 0; s < 4; ++s) {
            const int ks = s * 8;
            uint32_t a[2][4], b[4][2];
#pragma unroll
            for (int i = 0; i < 2; ++i) {
                a[i][0] = As[wm + i * 16 + gid][ks + tig];
                a[i][1] = As[wm + i * 16 + gid + 8][ks + tig];
                a[i][2] = As[wm + i * 16 + gid][ks + tig + 4];
                a[i][3] = As[wm + i * 16 + gid + 8][ks + tig + 4];
            }
#pragma unroll
            for (int j = 0; j < 4; ++j) {
                b[j][0] = Bs[ks + tig][wn + j * 8 + gid];
                b[j][1] = Bs[ks + tig + 4][wn + j * 8 + gid];
            }
#pragma unroll
            for (int i = 0; i < 2; ++i)
#pragma unroll
                for (int j = 0; j < 4; ++j)
                    mma8(acc[i][j], a[i][0], a[i][1], a[i][2], a[i][3], b[j][0], b[j][1]);
        }
        if (more) {
            __syncthreads();
#pragma unroll
            for (int p = 0; p < 4; ++p) {
                uint32_t* d = &As[lr + p * 32][lc];
                d[0] = f2tf(ra[p].x); d[1] = f2tf(ra[p].y);
                d[2] = f2tf(ra[p].z); d[3] = f2tf(ra[p].w);
            }
#pragma unroll
            for (int p = 0; p < 2; ++p) {
                uint32_t* d = &Bs[bk + p * 16][bn];
                d[0] = f2tf(rb[p].x); d[1] = f2tf(rb[p].y);
                d[2] = f2tf(rb[p].z); d[3] = f2tf(rb[p].w);
            }
            __syncthreads();
        }
    }

#pragma unroll
    for (int j = 0; j < 4; ++j) {
        const int c = col0 + wn + j * 8 + 2 * tig;
        float2 bj = *(const float2*)&bias[(size_t)e * N + c];
#pragma unroll
        for (int i = 0; i < 2; ++i) {
#pragma unroll
            for (int h = 0; h < 2; ++h) {
                const int m = wm + i * 16 + gid + h * 8;
                const int tok = rows[m];
                if (tok < 0) continue;
                float v0 = acc[i][j][h * 2 + 0] + bj.x;
                float v1 = acc[i][j][h * 2 + 1] + bj.y;
                if (GELU) {
                    v0 = 0.5f * v0 * (1.f + erff(v0 * 0.70710678118654752f));
                    v1 = 0.5f * v1 * (1.f + erff(v1 * 0.70710678118654752f));
                }
                if (RESID) {
                    float2 q = *(const float2*)&resid[(size_t)tok * N + c];
                    v0 += q.x; v1 += q.y;
                }
                *(float2*)&Y[(size_t)tok * N + c] = make_float2(v0, v1);
            }
        }
    }
}

// ---------------- flash attention, tf32 mma, 128-query tiles ----------------
// smem (dynamic): Qs[128][68], Ks[64][68], Vs[64][72], Ps[128][68]
#define FLASH_SMEM ((128 * 68 + 64 * 68 + 64 * 72 + 128 * 68) * 4)

__global__ void __launch_bounds__(256) flash_attn(
    const float* __restrict__ qb, int qs,
    const float* __restrict__ kb, int kstr,
    const float* __restrict__ vb, int vstr,
    float* __restrict__ out, int Lk)
{
    extern __shared__ uint32_t sm[];
    uint32_t* Qs = sm;                    // [128][68]
    uint32_t* Ks = Qs + 128 * 68;         // [64][68]
    uint32_t* Vs = Ks + 64 * 68;          // [64][72]
    uint32_t* Ps = Vs + 64 * 72;          // [128][68]

    const int t = threadIdx.x;
    const int lane = t & 31, wid = t >> 5;
    const int gid = lane >> 2, tig = lane & 3;
    const int m0 = wid * 16;
    const int b = blockIdx.x >> 3;
    const int h = blockIdx.x & 7;
    const int q0 = b * SEQ + blockIdx.y * 128;
    const int kbase = b * Lk;
    const int hoff = h * HDIM;

    // load Q (scaled by 1/8), cvt to tf32
    {
        const int r = t >> 1, c = (t & 1) * 32;
#pragma unroll
        for (int p = 0; p < 2; ++p) {
            const int rr = r + p * 128;   // rows 0..255? no: r in 0..127, p splits cols
            (void)rr;
        }
    }
#pragma unroll
    for (int p = 0; p < 8; ++p) {
        const int idx = t + p * 256;
        const int r = idx >> 4, c = (idx & 15) * 4;
        float4 v = *(const float4*)&qb[(size_t)(q0 + r) * qs + hoff + c];
        uint4 u;
        u.x = f2tf(v.x * 0.125f); u.y = f2tf(v.y * 0.125f);
        u.z = f2tf(v.z * 0.125f); u.w = f2tf(v.w * 0.125f);
        *(uint4*)&Qs[r * 68 + c] = u;
    }

    float oacc[8][4] = {};
    float m_i[2] = {-1e30f, -1e30f};
    float l_i[2] = {0.f, 0.f};

    for (int kt = 0; kt < Lk; kt += 64) {
        __syncthreads();   // prev PV done; Q ready on first iter
        // load K, V tiles (64 rows x 64 cols each)
#pragma unroll
        for (int p = 0; p < 4; ++p) {
            const int idx = t + p * 256;
            const int r = idx >> 4, c = (idx & 15) * 4;
            float4 kv = *(const float4*)&kb[(size_t)(kbase + kt + r) * kstr + hoff + c];
            uint4 u;
            u.x = f2tf(kv.x); u.y = f2tf(kv.y); u.z = f2tf(kv.z); u.w = f2tf(kv.w);
            *(uint4*)&Ks[r * 68 + c] = u;
            float4 vv = *(const float4*)&vb[(size_t)(kbase + kt + r) * vstr + hoff + c];
            uint4 w;
            w.x = f2tf(vv.x); w.y = f2tf(vv.y); w.z = f2tf(vv.z); w.w = f2tf(vv.w);
            *(uint4*)&Vs[r * 72 + c] = w;
        }
        __syncthreads();

        // S = Q @ K^T  (per warp: 16 rows x 64 keys)
        float sacc[8][4] = {};
#pragma unroll
        for (int s = 0; s < 8; ++s) {
            const int ks = s * 8;
            uint32_t a0 = Qs[(m0 + gid) * 68 + ks + tig];
            uint32_t a1 = Qs[(m0 + gid + 8) * 68 + ks + tig];
            uint32_t a2 = Qs[(m0 + gid) * 68 + ks + tig + 4];
            uint32_t a3 = Qs[(m0 + gid + 8) * 68 + ks + tig + 4];
#pragma unroll
            for (int nt = 0; nt < 8; ++nt) {
                uint32_t b0 = Ks[(nt * 8 + gid) * 68 + ks + tig];
                uint32_t b1 = Ks[(nt * 8 + gid) * 68 + ks + tig + 4];
                mma8(sacc[nt], a0, a1, a2, a3, b0, b1);
            }
        }

        // online softmax (rows gid and gid+8; reduce over the 4-lane quad)
        float mr0 = -1e30f, mr1 = -1e30f;
#pragma unroll
        for (int nt = 0; nt < 8; ++nt) {
            mr0 = fmaxf(mr0, fmaxf(sacc[nt][0], sacc[nt][1]));
            mr1 = fmaxf(mr1, fmaxf(sacc[nt][2], sacc[nt][3]));
        }
        mr0 = fmaxf(mr0, __shfl_xor_sync(0xffffffffu, mr0, 1));
        mr0 = fmaxf(mr0, __shfl_xor_sync(0xffffffffu, mr0, 2));
        mr1 = fmaxf(mr1, __shfl_xor_sync(0xffffffffu, mr1, 1));
        mr1 = fmaxf(mr1, __shfl_xor_sync(0xffffffffu, mr1, 2));
        const float mn0 = fmaxf(m_i[0], mr0);
        const float mn1 = fmaxf(m_i[1], mr1);
        const float al0 = __expf(m_i[0] - mn0);
        const float al1 = __expf(m_i[1] - mn1);
        m_i[0] = mn0; m_i[1] = mn1;
        float rs0 = 0.f, rs1 = 0.f;
#pragma unroll
        for (int nt = 0; nt < 8; ++nt) {
            sacc[nt][0] = __expf(sacc[nt][0] - mn0);
            sacc[nt][1] = __expf(sacc[nt][1] - mn0);
            sacc[nt][2] = __expf(sacc[nt][2] - mn1);
            sacc[nt][3] = __expf(sacc[nt][3] - mn1);
            rs0 += sacc[nt][0] + sacc[nt][1];
            rs1 += sacc[nt][2] + sacc[nt][3];
        }
        rs0 += __shfl_xor_sync(0xffffffffu, rs0, 1);
        rs0 += __shfl_xor_sync(0xffffffffu, rs0, 2);
        rs1 += __shfl_xor_sync(0xffffffffu, rs1, 1);
        rs1 += __shfl_xor_sync(0xffffffffu, rs1, 2);
        l_i[0] = l_i[0] * al0 + rs0;
        l_i[1] = l_i[1] * al1 + rs1;
#pragma unroll
        for (int nt = 0; nt < 8; ++nt) {
            oacc[nt][0] *= al0; oacc[nt][1] *= al0;
            oacc[nt][2] *= al1; oacc[nt][3] *= al1;
        }

        // write P (tf32) to smem for PV A-fragments
#pragma unroll
        for (int nt = 0; nt < 8; ++nt) {
            const int c = nt * 8 + 2 * tig;
            Ps[(m0 + gid) * 68 + c]     = f2tf(sacc[nt][0]);
            Ps[(m0 + gid) * 68 + c + 1] = f2tf(sacc[nt][1]);
            Ps[(m0 + gid + 8) * 68 + c]     = f2tf(sacc[nt][2]);
            Ps[(m0 + gid + 8) * 68 + c + 1] = f2tf(sacc[nt][3]);
        }
        __syncthreads();

        // O += P @ V
#pragma unroll
        for (int s = 0; s < 8; ++s) {
            const int ks = s * 8;
            uint32_t a0 = Ps[(m0 + gid) * 68 + ks + tig];
            uint32_t a1 = Ps[(m0 + gid + 8) * 68 + ks + tig];
            uint32_t a2 = Ps[(m0 + gid) * 68 + ks + tig + 4];
            uint32_t a3 = Ps[(m0 + gid + 8) * 68 + ks + tig + 4];
#pragma unroll
            for (int nt = 0; nt < 8; ++nt) {
                uint32_t b0 = Vs[(ks + tig) * 72 + nt * 8 + gid];
                uint32_t b1 = Vs[(ks + tig + 4) * 72 + nt * 8 + gid];
                mma8(oacc[nt], a0, a1, a2, a3, b0, b1);
            }
        }
    }

    const float inv0 = 1.f / l_i[0];
    const float inv1 = 1.f / l_i[1];
    const int r0 = q0 + m0 + gid;
#pragma unroll
    for (int nt = 0; nt < 8; ++nt) {
        const int c = hoff + nt * 8 + 2 * tig;
        *(float2*)&out[(size_t)r0 * DMODEL + c] =
            make_float2(oacc[nt][0] * inv0, oacc[nt][1] * inv0);
        *(float2*)&out[(size_t)(r0 + 8) * DMODEL + c] =
            make_float2(oacc[nt][2] * inv1, oacc[nt][3] * inv1);
    }
}

// ---------------- LayerNorm over D=512 -------------------------------------
__global__ void __launch_bounds__(128) layernorm_k(
    const float* __restrict__ in, const float* __restrict__ g,
    const float* __restrict__ bt, float* __restrict__ out)
{
    const int row = blockIdx.x;
    const int t = threadIdx.x;
    float4 v = *reinterpret_cast<const float4*>(&in[(size_t)row * 512 + t * 4]);
    float s  = v.x + v.y + v.z + v.w;
    float s2 = v.x * v.x + v.y * v.y + v.z * v.z + v.w * v.w;
#pragma unroll
    for (int off = 16; off >= 1; off >>= 1) {
        s  += __shfl_xor_sync(0xffffffffu, s,  off);
        s2 += __shfl_xor_sync(0xffffffffu, s2, off);
    }
    __shared__ float sh[8];
    int w = t >> 5;
    if ((t & 31) == 0) { sh[w] = s; sh[w + 4] = s2; }
    __syncthreads();
    float ts  = sh[0] + sh[1] + sh[2] + sh[3];
    float ts2 = sh[4] + sh[5] + sh[6] + sh[7];
    float mu  = ts * (1.f / 512.f);
    float var = ts2 * (1.f / 512.f) - mu * mu;
    float inv = rsqrtf(var + 1e-5f);
    float4 gg = *reinterpret_cast<const float4*>(&g[t * 4]);
    float4 bb = *reinterpret_cast<const float4*>(&bt[t * 4]);
    float4 o;
    o.x = (v.x - mu) * inv * gg.x + bb.x;
    o.y = (v.y - mu) * inv * gg.y + bb.y;
    o.z = (v.z - mu) * inv * gg.z + bb.z;
    o.w = (v.w - mu) * inv * gg.w + bb.w;
    *reinterpret_cast<float4*>(&out[(size_t)row * 512 + t * 4]) = o;
}

// ---------------- gate: top-1 routing ---------------------------------------
__global__ void __launch_bounds__(256) gate_k(
    const float* __restrict__ x, const float* __restrict__ gw,
    const float* __restrict__ gb)
{
    int warp = threadIdx.x >> 5, lane = threadIdx.x & 31;
    int tok = blockIdx.x * 8 + warp;
    float s0 = 0, s1 = 0, s2 = 0, s3 = 0;
    const float* xr = &x[(size_t)tok * 512];
#pragma unroll
    for (int d = lane * 4; d < 512; d += 128) {
        float4 xv = *reinterpret_cast<const float4*>(&xr[d]);
        float4 w0 = *reinterpret_cast<const float4*>(&gw[d]);
        float4 w1 = *reinterpret_cast<const float4*>(&gw[512 + d]);
        float4 w2 = *reinterpret_cast<const float4*>(&gw[1024 + d]);
        float4 w3 = *reinterpret_cast<const float4*>(&gw[1536 + d]);
        s0 += xv.x * w0.x + xv.y * w0.y + xv.z * w0.z + xv.w * w0.w;
        s1 += xv.x * w1.x + xv.y * w1.y + xv.z * w1.z + xv.w * w1.w;
        s2 += xv.x * w2.x + xv.y * w2.y + xv.z * w2.z + xv.w * w2.w;
        s3 += xv.x * w3.x + xv.y * w3.y + xv.z * w3.z + xv.w * w3.w;
    }
#pragma unroll
    for (int off = 16; off >= 1; off >>= 1) {
        s0 += __shfl_xor_sync(0xffffffffu, s0, off);
        s1 += __shfl_xor_sync(0xffffffffu, s1, off);
        s2 += __shfl_xor_sync(0xffffffffu, s2, off);
        s3 += __shfl_xor_sync(0xffffffffu, s3, off);
    }
    if (lane == 0) {
        s0 += gb[0]; s1 += gb[1]; s2 += gb[2]; s3 += gb[3];
        int best = 0; float bv = s0;
        if (s1 > bv) { bv = s1; best = 1; }
        if (s2 > bv) { bv = s2; best = 2; }
        if (s3 > bv) { bv = s3; best = 3; }
        int pos = atomicAdd(&g_cnt[best], 1);
        g_list[best * NTOK + pos] = tok;
    }
}

// ---------------- launch ----------------------------------------------------
extern "C" void kernel_launch(void* const* d_in, const int* in_sizes, int n_in,
                              void* d_out, int out_size)
{
    const float* x        = (const float*)d_in[0];
    const float* memory   = (const float*)d_in[1];
    const float* sa_in_w  = (const float*)d_in[2];
    const float* sa_in_b  = (const float*)d_in[3];
    const float* sa_out_w = (const float*)d_in[4];
    const float* sa_out_b = (const float*)d_in[5];
    const float* ca_in_w  = (const float*)d_in[6];
    const float* ca_in_b  = (const float*)d_in[7];
    const float* ca_out_w = (const float*)d_in[8];
    const float* ca_out_b = (const float*)d_in[9];
    const float* gate_w   = (const float*)d_in[10];
    const float* gate_b   = (const float*)d_in[11];
    const float* w1       = (const float*)d_in[12];
    const float* b1       = (const float*)d_in[13];
    const float* w2       = (const float*)d_in[14];
    const float* b2       = (const float*)d_in[15];
    const float* ln1_g    = (const float*)d_in[16];
    const float* ln1_b    = (const float*)d_in[17];
    const float* ln2_g    = (const float*)d_in[18];
    const float* ln2_b    = (const float*)d_in[19];
    const float* ln3_g    = (const float*)d_in[20];
    const float* ln3_b    = (const float*)d_in[21];
    float* out = (float*)d_out;

    float *qkv, *attn, *tmp, *x1, *x2, *hbuf;
    cudaGetSymbolAddress((void**)&qkv,  g_qkv);
    cudaGetSymbolAddress((void**)&attn, g_attn);
    cudaGetSymbolAddress((void**)&tmp,  g_tmp);
    cudaGetSymbolAddress((void**)&x1,   g_x1);
    cudaGetSymbolAddress((void**)&x2,   g_x2);
    cudaGetSymbolAddress((void**)&hbuf, g_h);

    cudaFuncSetAttribute(flash_attn, cudaFuncAttributeMaxDynamicSharedMemorySize,
                         FLASH_SMEM);

    zero_cnt_kernel<<<1, 32>>>();

    // --- self-attention ---
    gemm_nt<<<dim3(24, 64), 256>>>(x, sa_in_w, sa_in_b, nullptr, qkv, NTOK, 1536, 512);
    flash_attn<<<dim3(32, 16), 256, FLASH_SMEM>>>(qkv, 1536, qkv + 512, 1536,
                                                  qkv + 1024, 1536, attn, SEQ);
    gemm_nt<<<dim3(8, 64), 256>>>(attn, sa_out_w, sa_out_b, x, tmp, NTOK, 512, 512);
    layernorm_k<<<NTOK, 128>>>(tmp, ln1_g, ln1_b, x1);

    // --- cross-attention ---
    gemm_nt<<<dim3(8, 64), 256>>>(x1, ca_in_w, ca_in_b, nullptr, qkv, NTOK, 512, 512);
    gemm_nt<<<dim3(16, 64), 256>>>(memory, ca_in_w + 512 * 512, ca_in_b + 512, nullptr,
                                   qkv + (size_t)NTOK * 512, NTOK, 1024, 512);
    flash_attn<<<dim3(32, 16), 256, FLASH_SMEM>>>(qkv, 512,
                                                  qkv + (size_t)NTOK * 512, 1024,
                                                  qkv + (size_t)NTOK * 512 + 512, 1024,
                                                  attn, SEQ);
    gemm_nt<<<dim3(8, 64), 256>>>(attn, ca_out_w, ca_out_b, x1, tmp, NTOK, 512, 512);
    layernorm_k<<<NTOK, 128>>>(tmp, ln2_g, ln2_b, x2);

    // --- MoE FFN (top-1 routed) ---
    gate_k<<<NTOK / 8, 256>>>(x2, gate_w, gate_b);
    gemm_moe<true,  false><<<dim3(32, 256), 256>>>(x2,   w1, b1, nullptr, hbuf, 512, 2048);
    gemm_moe<false, true ><<<dim3(8,  256), 256>>>(hbuf, w2, b2, x2,      tmp,  2048, 512);
    layernorm_k<<<NTOK, 128>>>(tmp, ln3_g, ln3_b, out);
}

// round 3
// speedup vs baseline: 2.9518x; 1.0601x over previous
#include <cuda_runtime.h>
#include <math.h>
#include <stdint.h>

#define NTOK 8192      // B * L = 4 * 2048
#define DMODEL 512
#define HDIM 64
#define FDIM 2048
#define NEXP 4
#define SEQ 2048

// ---------------- scratch (device globals; no allocation allowed) ----------
__device__ float g_qkv[(size_t)NTOK * 1536];
__device__ float g_attn[(size_t)NTOK * DMODEL];
__device__ float g_tmp[(size_t)NTOK * DMODEL];
__device__ float g_x1[(size_t)NTOK * DMODEL];
__device__ float g_x2[(size_t)NTOK * DMODEL];
__device__ float g_h[(size_t)NTOK * FDIM];
__device__ int   g_cnt[NEXP];
__device__ int   g_list[NEXP * NTOK];

__global__ void zero_cnt_kernel() {
    if (threadIdx.x < NEXP) g_cnt[threadIdx.x] = 0;
}

// ---------------- tf32 / mma / ldmatrix helpers -----------------------------
__device__ __forceinline__ uint32_t f2tf(float f) {
    uint32_t u;
    asm("cvt.rna.tf32.f32 %0, %1;" : "=r"(u) : "f"(f));
    return u;
}

__device__ __forceinline__ void mma8(float* c, uint32_t a0, uint32_t a1,
                                     uint32_t a2, uint32_t a3,
                                     uint32_t b0, uint32_t b1) {
    asm volatile(
        "mma.sync.aligned.m16n8k8.row.col.f32.tf32.tf32.f32 "
        "{%0,%1,%2,%3},{%4,%5,%6,%7},{%8,%9},{%0,%1,%2,%3};"
        : "+f"(c[0]), "+f"(c[1]), "+f"(c[2]), "+f"(c[3])
        : "r"(a0), "r"(a1), "r"(a2), "r"(a3), "r"(b0), "r"(b1));
}

__device__ __forceinline__ void ldsm4(uint32_t& r0, uint32_t& r1,
                                      uint32_t& r2, uint32_t& r3, uint32_t addr) {
    asm volatile("ldmatrix.sync.aligned.m8n8.x4.shared.b16 {%0,%1,%2,%3}, [%4];"
                 : "=r"(r0), "=r"(r1), "=r"(r2), "=r"(r3) : "r"(addr));
}

__device__ __forceinline__ uint32_t smem_u32(const void* p) {
    return (uint32_t)__cvta_generic_to_shared(p);
}

// A-side ldmatrix lane offset (layout [row][k], stride S words), 16-row tile:
// lanes 0-15 -> rows 0..15 @ +0 ; lanes 16-31 -> rows 0..15 @ +4 words
__device__ __forceinline__ uint32_t a_lane_off(int lane, int S) {
    return (uint32_t)(((lane & 15) * S + ((lane >> 4) << 2)) << 2);
}
// B-side ldmatrix lane offset (layout [n][k], stride S words), 16-n tile:
// lanes 0-7 rows 0-7 @0, 8-15 rows 0-7 @+4, 16-23 rows 8-15 @0, 24-31 rows 8-15 @+4
__device__ __forceinline__ uint32_t b_lane_off(int lane, int S) {
    return (uint32_t)((((lane & 7) + ((lane >> 4) << 3)) * S +
                       (((lane >> 3) & 1) << 2)) << 2);
}

// ---------------- GEMM: C[M,N] = A[M,K] @ B[N,K]^T + bias (+resid) ---------
// 128x64x32 tile, 8 warps (4x2), warp tile 32x32, tf32 mma + ldmatrix
__global__ void __launch_bounds__(256) gemm_nt(
    const float* __restrict__ A, const float* __restrict__ Bw,
    const float* __restrict__ bias, const float* __restrict__ resid,
    float* __restrict__ C, int M, int N, int K)
{
    __shared__ uint32_t As[128][36];
    __shared__ uint32_t Bs[64][36];
    const int t = threadIdx.x;
    const int lane = t & 31, wid = t >> 5;
    const int gid = lane >> 2, tig = lane & 3;
    const int wm = (wid & 3) * 32, wn = (wid >> 2) * 32;
    const int row0 = blockIdx.y * 128, col0 = blockIdx.x * 64;
    const int lr = t >> 3, lc = (t & 7) * 4;

    const uint32_t a_ld = smem_u32(&As[wm][0]) + a_lane_off(lane, 36);
    const uint32_t b_ld = smem_u32(&Bs[wn][0]) + b_lane_off(lane, 36);
    const uint32_t A_HALF = 16 * 36 * 4;

    float4 ra[4], rb[2];
#pragma unroll
    for (int p = 0; p < 4; ++p)
        ra[p] = *(const float4*)&A[(size_t)(row0 + lr + p * 32) * K + lc];
#pragma unroll
    for (int p = 0; p < 2; ++p)
        rb[p] = *(const float4*)&Bw[(size_t)(col0 + lr + p * 32) * K + lc];
#pragma unroll
    for (int p = 0; p < 4; ++p) {
        uint32_t* d = &As[lr + p * 32][lc];
        d[0] = f2tf(ra[p].x); d[1] = f2tf(ra[p].y);
        d[2] = f2tf(ra[p].z); d[3] = f2tf(ra[p].w);
    }
#pragma unroll
    for (int p = 0; p < 2; ++p) {
        uint32_t* d = &Bs[lr + p * 32][lc];
        d[0] = f2tf(rb[p].x); d[1] = f2tf(rb[p].y);
        d[2] = f2tf(rb[p].z); d[3] = f2tf(rb[p].w);
    }
    __syncthreads();

    float acc[2][4][4] = {};
    for (int k0 = 0; k0 < K; k0 += 32) {
        const bool more = (k0 + 32) < K;
        if (more) {
#pragma unroll
            for (int p = 0; p < 4; ++p)
                ra[p] = *(const float4*)&A[(size_t)(row0 + lr + p * 32) * K + k0 + 32 + lc];
#pragma unroll
            for (int p = 0; p < 2; ++p)
                rb[p] = *(const float4*)&Bw[(size_t)(col0 + lr + p * 32) * K + k0 + 32 + lc];
        }
#pragma unroll
        for (int s = 0; s < 4; ++s) {
            uint32_t a0[4], a1[4], b0[4], b1[4];
            ldsm4(a0[0], a0[1], a0[2], a0[3], a_ld + s * 32);
            ldsm4(a1[0], a1[1], a1[2], a1[3], a_ld + s * 32 + A_HALF);
            ldsm4(b0[0], b0[1], b0[2], b0[3], b_ld + s * 32);
            ldsm4(b1[0], b1[1], b1[2], b1[3], b_ld + s * 32 + A_HALF);
            mma8(acc[0][0], a0[0], a0[1], a0[2], a0[3], b0[0], b0[1]);
            mma8(acc[0][1], a0[0], a0[1], a0[2], a0[3], b0[2], b0[3]);
            mma8(acc[0][2], a0[0], a0[1], a0[2], a0[3], b1[0], b1[1]);
            mma8(acc[0][3], a0[0], a0[1], a0[2], a0[3], b1[2], b1[3]);
            mma8(acc[1][0], a1[0], a1[1], a1[2], a1[3], b0[0], b0[1]);
            mma8(acc[1][1], a1[0], a1[1], a1[2], a1[3], b0[2], b0[3]);
            mma8(acc[1][2], a1[0], a1[1], a1[2], a1[3], b1[0], b1[1]);
            mma8(acc[1][3], a1[0], a1[1], a1[2], a1[3], b1[2], b1[3]);
        }
        if (more) {
            __syncthreads();
#pragma unroll
            for (int p = 0; p < 4; ++p) {
                uint32_t* d = &As[lr + p * 32][lc];
                d[0] = f2tf(ra[p].x); d[1] = f2tf(ra[p].y);
                d[2] = f2tf(ra[p].z); d[3] = f2tf(ra[p].w);
            }
#pragma unroll
            for (int p = 0; p < 2; ++p) {
                uint32_t* d = &Bs[lr + p * 32][lc];
                d[0] = f2tf(rb[p].x); d[1] = f2tf(rb[p].y);
                d[2] = f2tf(rb[p].z); d[3] = f2tf(rb[p].w);
            }
            __syncthreads();
        }
    }

#pragma unroll
    for (int j = 0; j < 4; ++j) {
        const int c = col0 + wn + j * 8 + 2 * tig;
        float2 bj = *(const float2*)&bias[c];
#pragma unroll
        for (int i = 0; i < 2; ++i) {
            const int r0 = row0 + wm + i * 16 + gid;
            float2 v0 = make_float2(acc[i][j][0] + bj.x, acc[i][j][1] + bj.y);
            float2 v1 = make_float2(acc[i][j][2] + bj.x, acc[i][j][3] + bj.y);
            if (resid) {
                float2 q0 = *(const float2*)&resid[(size_t)r0 * N + c];
                float2 q1 = *(const float2*)&resid[(size_t)(r0 + 8) * N + c];
                v0.x += q0.x; v0.y += q0.y; v1.x += q1.x; v1.y += q1.y;
            }
            *(float2*)&C[(size_t)r0 * N + c] = v0;
            *(float2*)&C[(size_t)(r0 + 8) * N + c] = v1;
        }
    }
}

// ---------------- MoE grouped GEMM (gather rows), W is [E][K][N] ------------
// A fragments via ldmatrix; B via conflict-free scalar LDS (stride 72)
template<bool GELU, bool RESID>
__global__ void __launch_bounds__(256) gemm_moe(
    const float* __restrict__ X, const float* __restrict__ W,
    const float* __restrict__ bias, const float* __restrict__ resid,
    float* __restrict__ Y, int K, int N)
{
    const int e = blockIdx.y >> 6;
    const int tile = blockIdx.y & 63;
    const int cnt = g_cnt[e];
    if (tile * 128 >= cnt) return;

    __shared__ uint32_t As[128][36];
    __shared__ uint32_t Bs[32][72];
    __shared__ int rows[128];
    const int t = threadIdx.x;
    if (t < 128) {
        int gi = tile * 128 + t;
        rows[t] = (gi < cnt) ? g_list[e * NTOK + gi] : -1;
    }
    __syncthreads();

    const int lane = t & 31, wid = t >> 5;
    const int gid = lane >> 2, tig = lane & 3;
    const int wm = (wid & 3) * 32, wn = (wid >> 2) * 32;
    const int col0 = blockIdx.x * 64;
    const float* We = W + (size_t)e * K * N;

    const int lr = t >> 3, lc = (t & 7) * 4;       // A tile mapping
    const int bk = t >> 4, bn = (t & 15) * 4;      // B tile mapping

    const uint32_t a_ld = smem_u32(&As[wm][0]) + a_lane_off(lane, 36);
    const uint32_t A_HALF = 16 * 36 * 4;

    float4 ra[4], rb[2];
#pragma unroll
    for (int p = 0; p < 4; ++p) {
        int r = rows[lr + p * 32];
        ra[p] = (r >= 0) ? *(const float4*)&X[(size_t)r * K + lc]
                         : make_float4(0.f, 0.f, 0.f, 0.f);
    }
#pragma unroll
    for (int p = 0; p < 2; ++p)
        rb[p] = *(const float4*)&We[(size_t)(bk + p * 16) * N + col0 + bn];
#pragma unroll
    for (int p = 0; p < 4; ++p) {
        uint32_t* d = &As[lr + p * 32][lc];
        d[0] = f2tf(ra[p].x); d[1] = f2tf(ra[p].y);
        d[2] = f2tf(ra[p].z); d[3] = f2tf(ra[p].w);
    }
#pragma unroll
    for (int p = 0; p < 2; ++p) {
        uint32_t* d = &Bs[bk + p * 16][bn];
        d[0] = f2tf(rb[p].x); d[1] = f2tf(rb[p].y);
        d[2] = f2tf(rb[p].z); d[3] = f2tf(rb[p].w);
    }
    __syncthreads();

    float acc[2][4][4] = {};
    for (int k0 = 0; k0 < K; k0 += 32) {
        const bool more = (k0 + 32) < K;
        if (more) {
#pragma unroll
            for (int p = 0; p < 4; ++p) {
                int r = rows[lr + p * 32];
                ra[p] = (r >= 0) ? *(const float4*)&X[(size_t)r * K + k0 + 32 + lc]
                                 : make_float4(0.f, 0.f, 0.f, 0.f);
            }
#pragma unroll
            for (int p = 0; p < 2; ++p)
                rb[p] = *(const float4*)&We[(size_t)(k0 + 32 + bk + p * 16) * N + col0 + bn];
        }
#pragma unroll
        for (int s = 0; s < 4; ++s) {
            const int ks = s * 8;
            uint32_t a0[4], a1[4], b[4][2];
            ldsm4(a0[0], a0[1], a0[2], a0[3], a_ld + s * 32);
            ldsm4(a1[0], a1[1], a1[2], a1[3], a_ld + s * 32 + A_HALF);
#pragma unroll
            for (int j = 0; j < 4; ++j) {
                b[j][0] = Bs[ks + tig][wn + j * 8 + gid];
                b[j][1] = Bs[ks + tig + 4][wn + j * 8 + gid];
            }
#pragma unroll
            for (int j = 0; j < 4; ++j) {
                mma8(acc[0][j], a0[0], a0[1], a0[2], a0[3], b[j][0], b[j][1]);
                mma8(acc[1][j], a1[0], a1[1], a1[2], a1[3], b[j][0], b[j][1]);
            }
        }
        if (more) {
            __syncthreads();
#pragma unroll
            for (int p = 0; p < 4; ++p) {
                uint32_t* d = &As[lr + p * 32][lc];
                d[0] = f2tf(ra[p].x); d[1] = f2tf(ra[p].y);
                d[2] = f2tf(ra[p].z); d[3] = f2tf(ra[p].w);
            }
#pragma unroll
            for (int p = 0; p < 2; ++p) {
                uint32_t* d = &Bs[bk + p * 16][bn];
                d[0] = f2tf(rb[p].x); d[1] = f2tf(rb[p].y);
                d[2] = f2tf(rb[p].z); d[3] = f2tf(rb[p].w);
            }
            __syncthreads();
        }
    }

#pragma unroll
    for (int j = 0; j < 4; ++j) {
        const int c = col0 + wn + j * 8 + 2 * tig;
        float2 bj = *(const float2*)&bias[(size_t)e * N + c];
#pragma unroll
        for (int i = 0; i < 2; ++i) {
#pragma unroll
            for (int h = 0; h < 2; ++h) {
                const int m = wm + i * 16 + gid + h * 8;
                const int tok = rows[m];
                if (tok < 0) continue;
                float v0 = acc[i][j][h * 2 + 0] + bj.x;
                float v1 = acc[i][j][h * 2 + 1] + bj.y;
                if (GELU) {
                    v0 = 0.5f * v0 * (1.f + erff(v0 * 0.70710678118654752f));
                    v1 = 0.5f * v1 * (1.f + erff(v1 * 0.70710678118654752f));
                }
                if (RESID) {
                    float2 q = *(const float2*)&resid[(size_t)tok * N + c];
                    v0 += q.x; v1 += q.y;
                }
                *(float2*)&Y[(size_t)tok * N + c] = make_float2(v0, v1);
            }
        }
    }
}

// ---------------- flash attention, tf32 mma + ldmatrix, 128-query tiles -----
// smem (dynamic): Qs[128][68], Ks[64][68], Vs[64][72], Ps[128][68]
#define FLASH_SMEM ((128 * 68 + 64 * 68 + 64 * 72 + 128 * 68) * 4)

__global__ void __launch_bounds__(256) flash_attn(
    const float* __restrict__ qb, int qs,
    const float* __restrict__ kb, int kstr,
    const float* __restrict__ vb, int vstr,
    float* __restrict__ out, int Lk)
{
    extern __shared__ uint32_t sm[];
    uint32_t* Qs = sm;                    // [128][68]
    uint32_t* Ks = Qs + 128 * 68;         // [64][68]
    uint32_t* Vs = Ks + 64 * 68;          // [64][72]  (k-major, scalar B loads)
    uint32_t* Ps = Vs + 64 * 72;          // [128][68]

    const int t = threadIdx.x;
    const int lane = t & 31, wid = t >> 5;
    const int gid = lane >> 2, tig = lane & 3;
    const int m0 = wid * 16;
    const int b = blockIdx.x >> 3;
    const int h = blockIdx.x & 7;
    const int q0 = b * SEQ + blockIdx.y * 128;
    const int kbase = b * Lk;
    const int hoff = h * HDIM;

    const uint32_t q_ld = smem_u32(&Qs[m0 * 68]) + a_lane_off(lane, 68);
    const uint32_t p_ld = smem_u32(&Ps[m0 * 68]) + a_lane_off(lane, 68);
    const uint32_t k_ld = smem_u32(&Ks[0]) + b_lane_off(lane, 68);
    const uint32_t K_HALF = 16 * 68 * 4;

    // load Q (scaled by 1/8), cvt to tf32
#pragma unroll
    for (int p = 0; p < 8; ++p) {
        const int idx = t + p * 256;
        const int r = idx >> 4, c = (idx & 15) * 4;
        float4 v = *(const float4*)&qb[(size_t)(q0 + r) * qs + hoff + c];
        uint4 u;
        u.x = f2tf(v.x * 0.125f); u.y = f2tf(v.y * 0.125f);
        u.z = f2tf(v.z * 0.125f); u.w = f2tf(v.w * 0.125f);
        *(uint4*)&Qs[r * 68 + c] = u;
    }

    float oacc[8][4] = {};
    float m_i[2] = {-1e30f, -1e30f};
    float l_i[2] = {0.f, 0.f};

    for (int kt = 0; kt < Lk; kt += 64) {
        __syncthreads();   // prev PV done; Q ready on first iter
#pragma unroll
        for (int p = 0; p < 4; ++p) {
            const int idx = t + p * 256;
            const int r = idx >> 4, c = (idx & 15) * 4;
            float4 kv = *(const float4*)&kb[(size_t)(kbase + kt + r) * kstr + hoff + c];
            uint4 u;
            u.x = f2tf(kv.x); u.y = f2tf(kv.y); u.z = f2tf(kv.z); u.w = f2tf(kv.w);
            *(uint4*)&Ks[r * 68 + c] = u;
            float4 vv = *(const float4*)&vb[(size_t)(kbase + kt + r) * vstr + hoff + c];
            uint4 w;
            w.x = f2tf(vv.x); w.y = f2tf(vv.y); w.z = f2tf(vv.z); w.w = f2tf(vv.w);
            *(uint4*)&Vs[r * 72 + c] = w;
        }
        __syncthreads();

        // S = Q @ K^T  (per warp: 16 rows x 64 keys)
        float sacc[8][4] = {};
#pragma unroll
        for (int s = 0; s < 8; ++s) {
            uint32_t a[4];
            ldsm4(a[0], a[1], a[2], a[3], q_ld + s * 32);
#pragma unroll
            for (int n4 = 0; n4 < 4; ++n4) {
                uint32_t bq[4];
                ldsm4(bq[0], bq[1], bq[2], bq[3], k_ld + s * 32 + n4 * K_HALF);
                mma8(sacc[n4 * 2],     a[0], a[1], a[2], a[3], bq[0], bq[1]);
                mma8(sacc[n4 * 2 + 1], a[0], a[1], a[2], a[3], bq[2], bq[3]);
            }
        }

        // online softmax (rows gid and gid+8; reduce over the 4-lane quad)
        float mr0 = -1e30f, mr1 = -1e30f;
#pragma unroll
        for (int nt = 0; nt < 8; ++nt) {
            mr0 = fmaxf(mr0, fmaxf(sacc[nt][0], sacc[nt][1]));
            mr1 = fmaxf(mr1, fmaxf(sacc[nt][2], sacc[nt][3]));
        }
        mr0 = fmaxf(mr0, __shfl_xor_sync(0xffffffffu, mr0, 1));
        mr0 = fmaxf(mr0, __shfl_xor_sync(0xffffffffu, mr0, 2));
        mr1 = fmaxf(mr1, __shfl_xor_sync(0xffffffffu, mr1, 1));
        mr1 = fmaxf(mr1, __shfl_xor_sync(0xffffffffu, mr1, 2));
        const float mn0 = fmaxf(m_i[0], mr0);
        const float mn1 = fmaxf(m_i[1], mr1);
        const float al0 = __expf(m_i[0] - mn0);
        const float al1 = __expf(m_i[1] - mn1);
        m_i[0] = mn0; m_i[1] = mn1;
        float rs0 = 0.f, rs1 = 0.f;
#pragma unroll
        for (int nt = 0; nt < 8; ++nt) {
            sacc[nt][0] = __expf(sacc[nt][0] - mn0);
            sacc[nt][1] = __expf(sacc[nt][1] - mn0);
            sacc[nt][2] = __expf(sacc[nt][2] - mn1);
            sacc[nt][3] = __expf(sacc[nt][3] - mn1);
            rs0 += sacc[nt][0] + sacc[nt][1];
            rs1 += sacc[nt][2] + sacc[nt][3];
        }
        rs0 += __shfl_xor_sync(0xffffffffu, rs0, 1);
        rs0 += __shfl_xor_sync(0xffffffffu, rs0, 2);
        rs1 += __shfl_xor_sync(0xffffffffu, rs1, 1);
        rs1 += __shfl_xor_sync(0xffffffffu, rs1, 2);
        l_i[0] = l_i[0] * al0 + rs0;
        l_i[1] = l_i[1] * al1 + rs1;
#pragma unroll
        for (int nt = 0; nt < 8; ++nt) {
            oacc[nt][0] *= al0; oacc[nt][1] *= al0;
            oacc[nt][2] *= al1; oacc[nt][3] *= al1;
        }

        // write P (tf32) to smem for PV A-fragments
#pragma unroll
        for (int nt = 0; nt < 8; ++nt) {
            const int c = nt * 8 + 2 * tig;
            Ps[(m0 + gid) * 68 + c]     = f2tf(sacc[nt][0]);
            Ps[(m0 + gid) * 68 + c + 1] = f2tf(sacc[nt][1]);
            Ps[(m0 + gid + 8) * 68 + c]     = f2tf(sacc[nt][2]);
            Ps[(m0 + gid + 8) * 68 + c + 1] = f2tf(sacc[nt][3]);
        }
        __syncthreads();

        // O += P @ V
#pragma unroll
        for (int s = 0; s < 8; ++s) {
            const int ks = s * 8;
            uint32_t a[4];
            ldsm4(a[0], a[1], a[2], a[3], p_ld + s * 32);
#pragma unroll
            for (int nt = 0; nt < 8; ++nt) {
                uint32_t b0 = Vs[(ks + tig) * 72 + nt * 8 + gid];
                uint32_t b1 = Vs[(ks + tig + 4) * 72 + nt * 8 + gid];
                mma8(oacc[nt], a[0], a[1], a[2], a[3], b0, b1);
            }
        }
    }

    const float inv0 = 1.f / l_i[0];
    const float inv1 = 1.f / l_i[1];
    const int r0 = q0 + m0 + gid;
#pragma unroll
    for (int nt = 0; nt < 8; ++nt) {
        const int c = hoff + nt * 8 + 2 * tig;
        *(float2*)&out[(size_t)r0 * DMODEL + c] =
            make_float2(oacc[nt][0] * inv0, oacc[nt][1] * inv0);
        *(float2*)&out[(size_t)(r0 + 8) * DMODEL + c] =
            make_float2(oacc[nt][2] * inv1, oacc[nt][3] * inv1);
    }
}

// ---------------- LayerNorm over D=512 -------------------------------------
__global__ void __launch_bounds__(128) layernorm_k(
    const float* __restrict__ in, const float* __restrict__ g,
    const float* __restrict__ bt, float* __restrict__ out)
{
    const int row = blockIdx.x;
    const int t = threadIdx.x;
    float4 v = *reinterpret_cast<const float4*>(&in[(size_t)row * 512 + t * 4]);
    float s  = v.x + v.y + v.z + v.w;
    float s2 = v.x * v.x + v.y * v.y + v.z * v.z + v.w * v.w;
#pragma unroll
    for (int off = 16; off >= 1; off >>= 1) {
        s  += __shfl_xor_sync(0xffffffffu, s,  off);
        s2 += __shfl_xor_sync(0xffffffffu, s2, off);
    }
    __shared__ float sh[8];
    int w = t >> 5;
    if ((t & 31) == 0) { sh[w] = s; sh[w + 4] = s2; }
    __syncthreads();
    float ts  = sh[0] + sh[1] + sh[2] + sh[3];
    float ts2 = sh[4] + sh[5] + sh[6] + sh[7];
    float mu  = ts * (1.f / 512.f);
    float var = ts2 * (1.f / 512.f) - mu * mu;
    float inv = rsqrtf(var + 1e-5f);
    float4 gg = *reinterpret_cast<const float4*>(&g[t * 4]);
    float4 bb = *reinterpret_cast<const float4*>(&bt[t * 4]);
    float4 o;
    o.x = (v.x - mu) * inv * gg.x + bb.x;
    o.y = (v.y - mu) * inv * gg.y + bb.y;
    o.z = (v.z - mu) * inv * gg.z + bb.z;
    o.w = (v.w - mu) * inv * gg.w + bb.w;
    *reinterpret_cast<float4*>(&out[(size_t)row * 512 + t * 4]) = o;
}

// ---------------- gate: top-1 routing ---------------------------------------
__global__ void __launch_bounds__(256) gate_k(
    const float* __restrict__ x, const float* __restrict__ gw,
    const float* __restrict__ gb)
{
    int warp = threadIdx.x >> 5, lane = threadIdx.x & 31;
    int tok = blockIdx.x * 8 + warp;
    float s0 = 0, s1 = 0, s2 = 0, s3 = 0;
    const float* xr = &x[(size_t)tok * 512];
#pragma unroll
    for (int d = lane * 4; d < 512; d += 128) {
        float4 xv = *reinterpret_cast<const float4*>(&xr[d]);
        float4 w0 = *reinterpret_cast<const float4*>(&gw[d]);
        float4 w1 = *reinterpret_cast<const float4*>(&gw[512 + d]);
        float4 w2 = *reinterpret_cast<const float4*>(&gw[1024 + d]);
        float4 w3 = *reinterpret_cast<const float4*>(&gw[1536 + d]);
        s0 += xv.x * w0.x + xv.y * w0.y + xv.z * w0.z + xv.w * w0.w;
        s1 += xv.x * w1.x + xv.y * w1.y + xv.z * w1.z + xv.w * w1.w;
        s2 += xv.x * w2.x + xv.y * w2.y + xv.z * w2.z + xv.w * w2.w;
        s3 += xv.x * w3.x + xv.y * w3.y + xv.z * w3.z + xv.w * w3.w;
    }
#pragma unroll
    for (int off = 16; off >= 1; off >>= 1) {
        s0 += __shfl_xor_sync(0xffffffffu, s0, off);
        s1 += __shfl_xor_sync(0xffffffffu, s1, off);
        s2 += __shfl_xor_sync(0xffffffffu, s2, off);
        s3 += __shfl_xor_sync(0xffffffffu, s3, off);
    }
    if (lane == 0) {
        s0 += gb[0]; s1 += gb[1]; s2 += gb[2]; s3 += gb[3];
        int best = 0; float bv = s0;
        if (s1 > bv) { bv = s1; best = 1; }
        if (s2 > bv) { bv = s2; best = 2; }
        if (s3 > bv) { bv = s3; best = 3; }
        int pos = atomicAdd(&g_cnt[best], 1);
        g_list[best * NTOK + pos] = tok;
    }
}

// ---------------- launch ----------------------------------------------------
extern "C" void kernel_launch(void* const* d_in, const int* in_sizes, int n_in,
                              void* d_out, int out_size)
{
    const float* x        = (const float*)d_in[0];
    const float* memory   = (const float*)d_in[1];
    const float* sa_in_w  = (const float*)d_in[2];
    const float* sa_in_b  = (const float*)d_in[3];
    const float* sa_out_w = (const float*)d_in[4];
    const float* sa_out_b = (const float*)d_in[5];
    const float* ca_in_w  = (const float*)d_in[6];
    const float* ca_in_b  = (const float*)d_in[7];
    const float* ca_out_w = (const float*)d_in[8];
    const float* ca_out_b = (const float*)d_in[9];
    const float* gate_w   = (const float*)d_in[10];
    const float* gate_b   = (const float*)d_in[11];
    const float* w1       = (const float*)d_in[12];
    const float* b1       = (const float*)d_in[13];
    const float* w2       = (const float*)d_in[14];
    const float* b2       = (const float*)d_in[15];
    const float* ln1_g    = (const float*)d_in[16];
    const float* ln1_b    = (const float*)d_in[17];
    const float* ln2_g    = (const float*)d_in[18];
    const float* ln2_b    = (const float*)d_in[19];
    const float* ln3_g    = (const float*)d_in[20];
    const float* ln3_b    = (const float*)d_in[21];
    float* out = (float*)d_out;

    float *qkv, *attn, *tmp, *x1, *x2, *hbuf;
    cudaGetSymbolAddress((void**)&qkv,  g_qkv);
    cudaGetSymbolAddress((void**)&attn, g_attn);
    cudaGetSymbolAddress((void**)&tmp,  g_tmp);
    cudaGetSymbolAddress((void**)&x1,   g_x1);
    cudaGetSymbolAddress((void**)&x2,   g_x2);
    cudaGetSymbolAddress((void**)&hbuf, g_h);

    cudaFuncSetAttribute(flash_attn, cudaFuncAttributeMaxDynamicSharedMemorySize,
                         FLASH_SMEM);

    zero_cnt_kernel<<<1, 32>>>();

    // --- self-attention ---
    gemm_nt<<<dim3(24, 64), 256>>>(x, sa_in_w, sa_in_b, nullptr, qkv, NTOK, 1536, 512);
    flash_attn<<<dim3(32, 16), 256, FLASH_SMEM>>>(qkv, 1536, qkv + 512, 1536,
                                                  qkv + 1024, 1536, attn, SEQ);
    gemm_nt<<<dim3(8, 64), 256>>>(attn, sa_out_w, sa_out_b, x, tmp, NTOK, 512, 512);
    layernorm_k<<<NTOK, 128>>>(tmp, ln1_g, ln1_b, x1);

    // --- cross-attention ---
    gemm_nt<<<dim3(8, 64), 256>>>(x1, ca_in_w, ca_in_b, nullptr, qkv, NTOK, 512, 512);
    gemm_nt<<<dim3(16, 64), 256>>>(memory, ca_in_w + 512 * 512, ca_in_b + 512, nullptr,
                                   qkv + (size_t)NTOK * 512, NTOK, 1024, 512);
    flash_attn<<<dim3(32, 16), 256, FLASH_SMEM>>>(qkv, 512,
                                                  qkv + (size_t)NTOK * 512, 1024,
                                                  qkv + (size_t)NTOK * 512 + 512, 1024,
                                                  attn, SEQ);
    gemm_nt<<<dim3(8, 64), 256>>>(attn, ca_out_w, ca_out_b, x1, tmp, NTOK, 512, 512);
    layernorm_k<<<NTOK, 128>>>(tmp, ln2_g, ln2_b, x2);

    // --- MoE FFN (top-1 routed) ---
    gate_k<<<NTOK / 8, 256>>>(x2, gate_w, gate_b);
    gemm_moe<true,  false><<<dim3(32, 256), 256>>>(x2,   w1, b1, nullptr, hbuf, 512, 2048);
    gemm_moe<false, true ><<<dim3(8,  256), 256>>>(hbuf, w2, b2, x2,      tmp,  2048, 512);
    layernorm_k<<<NTOK, 128>>>(tmp, ln3_g, ln3_b, out);
}

// round 4
// speedup vs baseline: 3.3746x; 1.1432x over previous
#include <cuda_runtime.h>
#include <math.h>
#include <stdint.h>

#define NTOK 8192      // B * L = 4 * 2048
#define DMODEL 512
#define HDIM 64
#define FDIM 2048
#define NEXP 4
#define SEQ 2048

// ---------------- scratch (device globals; no allocation allowed) ----------
__device__ float g_qkv[(size_t)NTOK * 1536];
__device__ float g_attn[(size_t)NTOK * DMODEL];
__device__ float g_tmp[(size_t)NTOK * DMODEL];
__device__ float g_x1[(size_t)NTOK * DMODEL];
__device__ float g_x2[(size_t)NTOK * DMODEL];
__device__ float g_h[(size_t)NTOK * FDIM];
__device__ int   g_cnt[NEXP];
__device__ int   g_list[NEXP * NTOK];

__global__ void zero_cnt_kernel() {
    if (threadIdx.x < NEXP) g_cnt[threadIdx.x] = 0;
}

// ---------------- mma / ldmatrix / cp.async helpers -------------------------
__device__ __forceinline__ void mma8(float* c, uint32_t a0, uint32_t a1,
                                     uint32_t a2, uint32_t a3,
                                     uint32_t b0, uint32_t b1) {
    asm volatile(
        "mma.sync.aligned.m16n8k8.row.col.f32.tf32.tf32.f32 "
        "{%0,%1,%2,%3},{%4,%5,%6,%7},{%8,%9},{%0,%1,%2,%3};"
        : "+f"(c[0]), "+f"(c[1]), "+f"(c[2]), "+f"(c[3])
        : "r"(a0), "r"(a1), "r"(a2), "r"(a3), "r"(b0), "r"(b1));
}

__device__ __forceinline__ void ldsm4(uint32_t& r0, uint32_t& r1,
                                      uint32_t& r2, uint32_t& r3, uint32_t addr) {
    asm volatile("ldmatrix.sync.aligned.m8n8.x4.shared.b16 {%0,%1,%2,%3}, [%4];"
                 : "=r"(r0), "=r"(r1), "=r"(r2), "=r"(r3) : "r"(addr));
}

__device__ __forceinline__ uint32_t smem_u32(const void* p) {
    return (uint32_t)__cvta_generic_to_shared(p);
}

__device__ __forceinline__ void cp16(uint32_t s, const void* g) {
    asm volatile("cp.async.cg.shared.global [%0], [%1], 16;"
                 :: "r"(s), "l"(g));
}
__device__ __forceinline__ void cp16p(uint32_t s, const void* g, bool pred) {
    int sz = pred ? 16 : 0;
    asm volatile("cp.async.cg.shared.global [%0], [%1], 16, %2;"
                 :: "r"(s), "l"(g), "r"(sz));
}
#define CP_COMMIT() asm volatile("cp.async.commit_group;" ::: "memory")
#define CP_WAIT0()  asm volatile("cp.async.wait_group 0;" ::: "memory")
#define CP_WAIT1()  asm volatile("cp.async.wait_group 1;" ::: "memory")

// A-side ldmatrix lane offset (layout [row][k], stride S words), 16-row tile
__device__ __forceinline__ uint32_t a_lane_off(int lane, int S) {
    return (uint32_t)(((lane & 15) * S + ((lane >> 4) << 2)) << 2);
}
// B-side ldmatrix lane offset (layout [n][k], stride S words), 16-n tile
__device__ __forceinline__ uint32_t b_lane_off(int lane, int S) {
    return (uint32_t)((((lane & 7) + ((lane >> 4) << 3)) * S +
                       (((lane >> 3) & 1) << 2)) << 2);
}

// ---------------- GEMM: C[M,N] = A[M,K] @ B[N,K]^T + bias (+resid) ---------
// 128x64x32 tile, 8 warps (4x2), cp.async 2-stage pipeline, tf32 mma + ldmatrix
#define GEMM_ASTG (128 * 36)
#define GEMM_BSTG (64 * 36)
#define GEMM_SMEM ((GEMM_ASTG + GEMM_BSTG) * 2 * 4)

__global__ void __launch_bounds__(256) gemm_nt(
    const float* __restrict__ A, const float* __restrict__ Bw,
    const float* __restrict__ bias, const float* __restrict__ resid,
    float* __restrict__ C, int M, int N, int K)
{
    extern __shared__ uint32_t dsm[];
    uint32_t* As = dsm;                       // [2][128][36]
    uint32_t* Bs = dsm + 2 * GEMM_ASTG;       // [2][64][36]
    const int t = threadIdx.x;
    const int lane = t & 31, wid = t >> 5;
    const int gid = lane >> 2, tig = lane & 3;
    const int wm = (wid & 3) * 32, wn = (wid >> 2) * 32;
    const int row0 = blockIdx.y * 128, col0 = blockIdx.x * 64;
    const int lr = t >> 3, lc = (t & 7) * 4;

    const uint32_t as_st = smem_u32(As) + (uint32_t)((lr * 36 + lc) << 2);
    const uint32_t bs_st = smem_u32(Bs) + (uint32_t)((lr * 36 + lc) << 2);
    const uint32_t a_ld0 = smem_u32(As) + (uint32_t)((wm * 36) << 2) + a_lane_off(lane, 36);
    const uint32_t b_ld0 = smem_u32(Bs) + (uint32_t)((wn * 36) << 2) + b_lane_off(lane, 36);
    const uint32_t A_HALF = 16 * 36 * 4;

    const int nIter = K >> 5;
    // prologue: stage 0
#pragma unroll
    for (int p = 0; p < 4; ++p)
        cp16(as_st + (uint32_t)(p * 32 * 36 * 4), &A[(size_t)(row0 + lr + p * 32) * K + lc]);
#pragma unroll
    for (int p = 0; p < 2; ++p)
        cp16(bs_st + (uint32_t)(p * 32 * 36 * 4), &Bw[(size_t)(col0 + lr + p * 32) * K + lc]);
    CP_COMMIT();

    float acc[2][4][4] = {};
    for (int it = 0; it < nIter; ++it) {
        const int cur = it & 1;
        const bool more = (it + 1) < nIter;
        if (more) {
            const int k0 = (it + 1) << 5;
            const uint32_t so = (uint32_t)(((cur ^ 1) ? GEMM_ASTG : 0) << 2);
            const uint32_t sb = (uint32_t)(((cur ^ 1) ? GEMM_BSTG : 0) << 2);
#pragma unroll
            for (int p = 0; p < 4; ++p)
                cp16(as_st + so + (uint32_t)(p * 32 * 36 * 4),
                     &A[(size_t)(row0 + lr + p * 32) * K + k0 + lc]);
#pragma unroll
            for (int p = 0; p < 2; ++p)
                cp16(bs_st + sb + (uint32_t)(p * 32 * 36 * 4),
                     &Bw[(size_t)(col0 + lr + p * 32) * K + k0 + lc]);
            CP_COMMIT();
            CP_WAIT1();
        } else {
            CP_WAIT0();
        }
        __syncthreads();
        const uint32_t a_ld = a_ld0 + (uint32_t)((cur ? GEMM_ASTG : 0) << 2);
        const uint32_t b_ld = b_ld0 + (uint32_t)((cur ? GEMM_BSTG : 0) << 2);
#pragma unroll
        for (int s = 0; s < 4; ++s) {
            uint32_t a0[4], a1[4], b0[4], b1[4];
            ldsm4(a0[0], a0[1], a0[2], a0[3], a_ld + s * 32);
            ldsm4(a1[0], a1[1], a1[2], a1[3], a_ld + s * 32 + A_HALF);
            ldsm4(b0[0], b0[1], b0[2], b0[3], b_ld + s * 32);
            ldsm4(b1[0], b1[1], b1[2], b1[3], b_ld + s * 32 + A_HALF);
            mma8(acc[0][0], a0[0], a0[1], a0[2], a0[3], b0[0], b0[1]);
            mma8(acc[0][1], a0[0], a0[1], a0[2], a0[3], b0[2], b0[3]);
            mma8(acc[0][2], a0[0], a0[1], a0[2], a0[3], b1[0], b1[1]);
            mma8(acc[0][3], a0[0], a0[1], a0[2], a0[3], b1[2], b1[3]);
            mma8(acc[1][0], a1[0], a1[1], a1[2], a1[3], b0[0], b0[1]);
            mma8(acc[1][1], a1[0], a1[1], a1[2], a1[3], b0[2], b0[3]);
            mma8(acc[1][2], a1[0], a1[1], a1[2], a1[3], b1[0], b1[1]);
            mma8(acc[1][3], a1[0], a1[1], a1[2], a1[3], b1[2], b1[3]);
        }
        __syncthreads();
    }

#pragma unroll
    for (int j = 0; j < 4; ++j) {
        const int c = col0 + wn + j * 8 + 2 * tig;
        float2 bj = *(const float2*)&bias[c];
#pragma unroll
        for (int i = 0; i < 2; ++i) {
            const int r0 = row0 + wm + i * 16 + gid;
            float2 v0 = make_float2(acc[i][j][0] + bj.x, acc[i][j][1] + bj.y);
            float2 v1 = make_float2(acc[i][j][2] + bj.x, acc[i][j][3] + bj.y);
            if (resid) {
                float2 q0 = *(const float2*)&resid[(size_t)r0 * N + c];
                float2 q1 = *(const float2*)&resid[(size_t)(r0 + 8) * N + c];
                v0.x += q0.x; v0.y += q0.y; v1.x += q1.x; v1.y += q1.y;
            }
            *(float2*)&C[(size_t)r0 * N + c] = v0;
            *(float2*)&C[(size_t)(r0 + 8) * N + c] = v1;
        }
    }
}

// ---------------- MoE grouped GEMM (gather rows), W is [E][K][N] ------------
#define MOE_ASTG (128 * 36)
#define MOE_BSTG (32 * 72)
#define MOE_SMEM ((MOE_ASTG + MOE_BSTG) * 2 * 4)

template<bool GELU, bool RESID>
__global__ void __launch_bounds__(256) gemm_moe(
    const float* __restrict__ X, const float* __restrict__ W,
    const float* __restrict__ bias, const float* __restrict__ resid,
    float* __restrict__ Y, int K, int N)
{
    const int e = blockIdx.y >> 6;
    const int tile = blockIdx.y & 63;
    const int cnt = g_cnt[e];
    if (tile * 128 >= cnt) return;

    extern __shared__ uint32_t dsm[];
    uint32_t* As = dsm;                    // [2][128][36]
    uint32_t* Bs = dsm + 2 * MOE_ASTG;     // [2][32][72]
    __shared__ int rows[128];
    const int t = threadIdx.x;
    if (t < 128) {
        int gi = tile * 128 + t;
        rows[t] = (gi < cnt) ? g_list[e * NTOK + gi] : -1;
    }
    __syncthreads();

    const int lane = t & 31, wid = t >> 5;
    const int gid = lane >> 2, tig = lane & 3;
    const int wm = (wid & 3) * 32, wn = (wid >> 2) * 32;
    const int col0 = blockIdx.x * 64;
    const float* We = W + (size_t)e * K * N;

    const int lr = t >> 3, lc = (t & 7) * 4;       // A tile mapping
    const int bk = t >> 4, bn = (t & 15) * 4;      // B tile mapping

    const uint32_t as_st = smem_u32(As) + (uint32_t)((lr * 36 + lc) << 2);
    const uint32_t bs_st = smem_u32(Bs) + (uint32_t)((bk * 72 + bn) << 2);
    const uint32_t a_ld0 = smem_u32(As) + (uint32_t)((wm * 36) << 2) + a_lane_off(lane, 36);
    const uint32_t A_HALF = 16 * 36 * 4;

    int rws[4];
    bool rok[4];
#pragma unroll
    for (int p = 0; p < 4; ++p) {
        rws[p] = rows[lr + p * 32];
        rok[p] = rws[p] >= 0;
        if (!rok[p]) rws[p] = 0;
    }

    const int nIter = K >> 5;
#pragma unroll
    for (int p = 0; p < 4; ++p)
        cp16p(as_st + (uint32_t)(p * 32 * 36 * 4),
              &X[(size_t)rws[p] * K + lc], rok[p]);
#pragma unroll
    for (int p = 0; p < 2; ++p)
        cp16(bs_st + (uint32_t)(p * 16 * 72 * 4),
             &We[(size_t)(bk + p * 16) * N + col0 + bn]);
    CP_COMMIT();

    float acc[2][4][4] = {};
    for (int it = 0; it < nIter; ++it) {
        const int cur = it & 1;
        const bool more = (it + 1) < nIter;
        if (more) {
            const int k0 = (it + 1) << 5;
            const uint32_t so = (uint32_t)(((cur ^ 1) ? MOE_ASTG : 0) << 2);
            const uint32_t sb = (uint32_t)(((cur ^ 1) ? MOE_BSTG : 0) << 2);
#pragma unroll
            for (int p = 0; p < 4; ++p)
                cp16p(as_st + so + (uint32_t)(p * 32 * 36 * 4),
                      &X[(size_t)rws[p] * K + k0 + lc], rok[p]);
#pragma unroll
            for (int p = 0; p < 2; ++p)
                cp16(bs_st + sb + (uint32_t)(p * 16 * 72 * 4),
                     &We[(size_t)(k0 + bk + p * 16) * N + col0 + bn]);
            CP_COMMIT();
            CP_WAIT1();
        } else {
            CP_WAIT0();
        }
        __syncthreads();
        const uint32_t a_ld = a_ld0 + (uint32_t)((cur ? MOE_ASTG : 0) << 2);
        const uint32_t* Bc = Bs + (cur ? MOE_BSTG : 0);
#pragma unroll
        for (int s = 0; s < 4; ++s) {
            const int ks = s * 8;
            uint32_t a0[4], a1[4], b[4][2];
            ldsm4(a0[0], a0[1], a0[2], a0[3], a_ld + s * 32);
            ldsm4(a1[0], a1[1], a1[2], a1[3], a_ld + s * 32 + A_HALF);
#pragma unroll
            for (int j = 0; j < 4; ++j) {
                b[j][0] = Bc[(ks + tig) * 72 + wn + j * 8 + gid];
                b[j][1] = Bc[(ks + tig + 4) * 72 + wn + j * 8 + gid];
            }
#pragma unroll
            for (int j = 0; j < 4; ++j) {
                mma8(acc[0][j], a0[0], a0[1], a0[2], a0[3], b[j][0], b[j][1]);
                mma8(acc[1][j], a1[0], a1[1], a1[2], a1[3], b[j][0], b[j][1]);
            }
        }
        __syncthreads();
    }

#pragma unroll
    for (int j = 0; j < 4; ++j) {
        const int c = col0 + wn + j * 8 + 2 * tig;
        float2 bj = *(const float2*)&bias[(size_t)e * N + c];
#pragma unroll
        for (int i = 0; i < 2; ++i) {
#pragma unroll
            for (int h = 0; h < 2; ++h) {
                const int m = wm + i * 16 + gid + h * 8;
                const int tok = rows[m];
                if (tok < 0) continue;
                float v0 = acc[i][j][h * 2 + 0] + bj.x;
                float v1 = acc[i][j][h * 2 + 1] + bj.y;
                if (GELU) {
                    v0 = 0.5f * v0 * (1.f + erff(v0 * 0.70710678118654752f));
                    v1 = 0.5f * v1 * (1.f + erff(v1 * 0.70710678118654752f));
                }
                if (RESID) {
                    float2 q = *(const float2*)&resid[(size_t)tok * N + c];
                    v0 += q.x; v1 += q.y;
                }
                *(float2*)&Y[(size_t)tok * N + c] = make_float2(v0, v1);
            }
        }
    }
}

// ---------------- flash attention, tf32 mma + ldmatrix, 128-query tiles -----
#define FLASH_SMEM ((128 * 68 + 64 * 68 + 64 * 72 + 128 * 68) * 4)

__global__ void __launch_bounds__(256) flash_attn(
    const float* __restrict__ qb, int qs,
    const float* __restrict__ kb, int kstr,
    const float* __restrict__ vb, int vstr,
    float* __restrict__ out, int Lk)
{
    extern __shared__ uint32_t sm[];
    uint32_t* Qs = sm;                    // [128][68]
    uint32_t* Ks = Qs + 128 * 68;         // [64][68]
    uint32_t* Vs = Ks + 64 * 68;          // [64][72]  (k-major, scalar B loads)
    uint32_t* Ps = Vs + 64 * 72;          // [128][68]

    const int t = threadIdx.x;
    const int lane = t & 31, wid = t >> 5;
    const int gid = lane >> 2, tig = lane & 3;
    const int m0 = wid * 16;
    const int b = blockIdx.x >> 3;
    const int h = blockIdx.x & 7;
    const int q0 = b * SEQ + blockIdx.y * 128;
    const int kbase = b * Lk;
    const int hoff = h * HDIM;

    const uint32_t q_ld = smem_u32(&Qs[m0 * 68]) + a_lane_off(lane, 68);
    const uint32_t p_ld = smem_u32(&Ps[m0 * 68]) + a_lane_off(lane, 68);
    const uint32_t k_ld = smem_u32(&Ks[0]) + b_lane_off(lane, 68);
    const uint32_t K_HALF = 16 * 68 * 4;
    const uint32_t ks_base = smem_u32(Ks);
    const uint32_t vs_base = smem_u32(Vs);

    // load Q (scaled by 1/8), raw fp32 bits as tf32
#pragma unroll
    for (int p = 0; p < 8; ++p) {
        const int idx = t + p * 256;
        const int r = idx >> 4, c = (idx & 15) * 4;
        float4 v = *(const float4*)&qb[(size_t)(q0 + r) * qs + hoff + c];
        uint4 u;
        u.x = __float_as_uint(v.x * 0.125f); u.y = __float_as_uint(v.y * 0.125f);
        u.z = __float_as_uint(v.z * 0.125f); u.w = __float_as_uint(v.w * 0.125f);
        *(uint4*)&Qs[r * 68 + c] = u;
    }

    float oacc[8][4] = {};
    float m_i[2] = {-1e30f, -1e30f};
    float l_i[2] = {0.f, 0.f};

    for (int kt = 0; kt < Lk; kt += 64) {
        __syncthreads();   // prev PV / QK done with Ks,Vs
#pragma unroll
        for (int p = 0; p < 4; ++p) {
            const int idx = t + p * 256;
            const int r = idx >> 4, c = (idx & 15) * 4;
            cp16(ks_base + (uint32_t)((r * 68 + c) << 2),
                 &kb[(size_t)(kbase + kt + r) * kstr + hoff + c]);
            cp16(vs_base + (uint32_t)((r * 72 + c) << 2),
                 &vb[(size_t)(kbase + kt + r) * vstr + hoff + c]);
        }
        CP_COMMIT();
        CP_WAIT0();
        __syncthreads();

        // S = Q @ K^T  (per warp: 16 rows x 64 keys)
        float sacc[8][4] = {};
#pragma unroll
        for (int s = 0; s < 8; ++s) {
            uint32_t a[4];
            ldsm4(a[0], a[1], a[2], a[3], q_ld + s * 32);
#pragma unroll
            for (int n4 = 0; n4 < 4; ++n4) {
                uint32_t bq[4];
                ldsm4(bq[0], bq[1], bq[2], bq[3], k_ld + s * 32 + n4 * K_HALF);
                mma8(sacc[n4 * 2],     a[0], a[1], a[2], a[3], bq[0], bq[1]);
                mma8(sacc[n4 * 2 + 1], a[0], a[1], a[2], a[3], bq[2], bq[3]);
            }
        }

        // online softmax (rows gid and gid+8; reduce over the 4-lane quad)
        float mr0 = -1e30f, mr1 = -1e30f;
#pragma unroll
        for (int nt = 0; nt < 8; ++nt) {
            mr0 = fmaxf(mr0, fmaxf(sacc[nt][0], sacc[nt][1]));
            mr1 = fmaxf(mr1, fmaxf(sacc[nt][2], sacc[nt][3]));
        }
        mr0 = fmaxf(mr0, __shfl_xor_sync(0xffffffffu, mr0, 1));
        mr0 = fmaxf(mr0, __shfl_xor_sync(0xffffffffu, mr0, 2));
        mr1 = fmaxf(mr1, __shfl_xor_sync(0xffffffffu, mr1, 1));
        mr1 = fmaxf(mr1, __shfl_xor_sync(0xffffffffu, mr1, 2));
        const float mn0 = fmaxf(m_i[0], mr0);
        const float mn1 = fmaxf(m_i[1], mr1);
        const float al0 = __expf(m_i[0] - mn0);
        const float al1 = __expf(m_i[1] - mn1);
        m_i[0] = mn0; m_i[1] = mn1;
        float rs0 = 0.f, rs1 = 0.f;
#pragma unroll
        for (int nt = 0; nt < 8; ++nt) {
            sacc[nt][0] = __expf(sacc[nt][0] - mn0);
            sacc[nt][1] = __expf(sacc[nt][1] - mn0);
            sacc[nt][2] = __expf(sacc[nt][2] - mn1);
            sacc[nt][3] = __expf(sacc[nt][3] - mn1);
            rs0 += sacc[nt][0] + sacc[nt][1];
            rs1 += sacc[nt][2] + sacc[nt][3];
        }
        rs0 += __shfl_xor_sync(0xffffffffu, rs0, 1);
        rs0 += __shfl_xor_sync(0xffffffffu, rs0, 2);
        rs1 += __shfl_xor_sync(0xffffffffu, rs1, 1);
        rs1 += __shfl_xor_sync(0xffffffffu, rs1, 2);
        l_i[0] = l_i[0] * al0 + rs0;
        l_i[1] = l_i[1] * al1 + rs1;
#pragma unroll
        for (int nt = 0; nt < 8; ++nt) {
            oacc[nt][0] *= al0; oacc[nt][1] *= al0;
            oacc[nt][2] *= al1; oacc[nt][3] *= al1;
        }

        // write P (raw bits) to smem for PV A-fragments
#pragma unroll
        for (int nt = 0; nt < 8; ++nt) {
            const int c = nt * 8 + 2 * tig;
            Ps[(m0 + gid) * 68 + c]     = __float_as_uint(sacc[nt][0]);
            Ps[(m0 + gid) * 68 + c + 1] = __float_as_uint(sacc[nt][1]);
            Ps[(m0 + gid + 8) * 68 + c]     = __float_as_uint(sacc[nt][2]);
            Ps[(m0 + gid + 8) * 68 + c + 1] = __float_as_uint(sacc[nt][3]);
        }
        __syncthreads();

        // O += P @ V
#pragma unroll
        for (int s = 0; s < 8; ++s) {
            const int ks = s * 8;
            uint32_t a[4];
            ldsm4(a[0], a[1], a[2], a[3], p_ld + s * 32);
#pragma unroll
            for (int nt = 0; nt < 8; ++nt) {
                uint32_t b0 = Vs[(ks + tig) * 72 + nt * 8 + gid];
                uint32_t b1 = Vs[(ks + tig + 4) * 72 + nt * 8 + gid];
                mma8(oacc[nt], a[0], a[1], a[2], a[3], b0, b1);
            }
        }
    }

    const float inv0 = 1.f / l_i[0];
    const float inv1 = 1.f / l_i[1];
    const int r0 = q0 + m0 + gid;
#pragma unroll
    for (int nt = 0; nt < 8; ++nt) {
        const int c = hoff + nt * 8 + 2 * tig;
        *(float2*)&out[(size_t)r0 * DMODEL + c] =
            make_float2(oacc[nt][0] * inv0, oacc[nt][1] * inv0);
        *(float2*)&out[(size_t)(r0 + 8) * DMODEL + c] =
            make_float2(oacc[nt][2] * inv1, oacc[nt][3] * inv1);
    }
}

// ---------------- LayerNorm over D=512 -------------------------------------
__global__ void __launch_bounds__(128) layernorm_k(
    const float* __restrict__ in, const float* __restrict__ g,
    const float* __restrict__ bt, float* __restrict__ out)
{
    const int row = blockIdx.x;
    const int t = threadIdx.x;
    float4 v = *reinterpret_cast<const float4*>(&in[(size_t)row * 512 + t * 4]);
    float s  = v.x + v.y + v.z + v.w;
    float s2 = v.x * v.x + v.y * v.y + v.z * v.z + v.w * v.w;
#pragma unroll
    for (int off = 16; off >= 1; off >>= 1) {
        s  += __shfl_xor_sync(0xffffffffu, s,  off);
        s2 += __shfl_xor_sync(0xffffffffu, s2, off);
    }
    __shared__ float sh[8];
    int w = t >> 5;
    if ((t & 31) == 0) { sh[w] = s; sh[w + 4] = s2; }
    __syncthreads();
    float ts  = sh[0] + sh[1] + sh[2] + sh[3];
    float ts2 = sh[4] + sh[5] + sh[6] + sh[7];
    float mu  = ts * (1.f / 512.f);
    float var = ts2 * (1.f / 512.f) - mu * mu;
    float inv = rsqrtf(var + 1e-5f);
    float4 gg = *reinterpret_cast<const float4*>(&g[t * 4]);
    float4 bb = *reinterpret_cast<const float4*>(&bt[t * 4]);
    float4 o;
    o.x = (v.x - mu) * inv * gg.x + bb.x;
    o.y = (v.y - mu) * inv * gg.y + bb.y;
    o.z = (v.z - mu) * inv * gg.z + bb.z;
    o.w = (v.w - mu) * inv * gg.w + bb.w;
    *reinterpret_cast<float4*>(&out[(size_t)row * 512 + t * 4]) = o;
}

// ---------------- gate: top-1 routing ---------------------------------------
__global__ void __launch_bounds__(256) gate_k(
    const float* __restrict__ x, const float* __restrict__ gw,
    const float* __restrict__ gb)
{
    int warp = threadIdx.x >> 5, lane = threadIdx.x & 31;
    int tok = blockIdx.x * 8 + warp;
    float s0 = 0, s1 = 0, s2 = 0, s3 = 0;
    const float* xr = &x[(size_t)tok * 512];
#pragma unroll
    for (int d = lane * 4; d < 512; d += 128) {
        float4 xv = *reinterpret_cast<const float4*>(&xr[d]);
        float4 w0 = *reinterpret_cast<const float4*>(&gw[d]);
        float4 w1 = *reinterpret_cast<const float4*>(&gw[512 + d]);
        float4 w2 = *reinterpret_cast<const float4*>(&gw[1024 + d]);
        float4 w3 = *reinterpret_cast<const float4*>(&gw[1536 + d]);
        s0 += xv.x * w0.x + xv.y * w0.y + xv.z * w0.z + xv.w * w0.w;
        s1 += xv.x * w1.x + xv.y * w1.y + xv.z * w1.z + xv.w * w1.w;
        s2 += xv.x * w2.x + xv.y * w2.y + xv.z * w2.z + xv.w * w2.w;
        s3 += xv.x * w3.x + xv.y * w3.y + xv.z * w3.z + xv.w * w3.w;
    }
#pragma unroll
    for (int off = 16; off >= 1; off >>= 1) {
        s0 += __shfl_xor_sync(0xffffffffu, s0, off);
        s1 += __shfl_xor_sync(0xffffffffu, s1, off);
        s2 += __shfl_xor_sync(0xffffffffu, s2, off);
        s3 += __shfl_xor_sync(0xffffffffu, s3, off);
    }
    if (lane == 0) {
        s0 += gb[0]; s1 += gb[1]; s2 += gb[2]; s3 += gb[3];
        int best = 0; float bv = s0;
        if (s1 > bv) { bv = s1; best = 1; }
        if (s2 > bv) { bv = s2; best = 2; }
        if (s3 > bv) { bv = s3; best = 3; }
        int pos = atomicAdd(&g_cnt[best], 1);
        g_list[best * NTOK + pos] = tok;
    }
}

// ---------------- launch ----------------------------------------------------
extern "C" void kernel_launch(void* const* d_in, const int* in_sizes, int n_in,
                              void* d_out, int out_size)
{
    const float* x        = (const float*)d_in[0];
    const float* memory   = (const float*)d_in[1];
    const float* sa_in_w  = (const float*)d_in[2];
    const float* sa_in_b  = (const float*)d_in[3];
    const float* sa_out_w = (const float*)d_in[4];
    const float* sa_out_b = (const float*)d_in[5];
    const float* ca_in_w  = (const float*)d_in[6];
    const float* ca_in_b  = (const float*)d_in[7];
    const float* ca_out_w = (const float*)d_in[8];
    const float* ca_out_b = (const float*)d_in[9];
    const float* gate_w   = (const float*)d_in[10];
    const float* gate_b   = (const float*)d_in[11];
    const float* w1       = (const float*)d_in[12];
    const float* b1       = (const float*)d_in[13];
    const float* w2       = (const float*)d_in[14];
    const float* b2       = (const float*)d_in[15];
    const float* ln1_g    = (const float*)d_in[16];
    const float* ln1_b    = (const float*)d_in[17];
    const float* ln2_g    = (const float*)d_in[18];
    const float* ln2_b    = (const float*)d_in[19];
    const float* ln3_g    = (const float*)d_in[20];
    const float* ln3_b    = (const float*)d_in[21];
    float* out = (float*)d_out;

    float *qkv, *attn, *tmp, *x1, *x2, *hbuf;
    cudaGetSymbolAddress((void**)&qkv,  g_qkv);
    cudaGetSymbolAddress((void**)&attn, g_attn);
    cudaGetSymbolAddress((void**)&tmp,  g_tmp);
    cudaGetSymbolAddress((void**)&x1,   g_x1);
    cudaGetSymbolAddress((void**)&x2,   g_x2);
    cudaGetSymbolAddress((void**)&hbuf, g_h);

    cudaFuncSetAttribute(flash_attn, cudaFuncAttributeMaxDynamicSharedMemorySize,
                         FLASH_SMEM);
    cudaFuncSetAttribute(gemm_nt, cudaFuncAttributeMaxDynamicSharedMemorySize,
                         GEMM_SMEM);
    cudaFuncSetAttribute(gemm_moe<true, false>,
                         cudaFuncAttributeMaxDynamicSharedMemorySize, MOE_SMEM);
    cudaFuncSetAttribute(gemm_moe<false, true>,
                         cudaFuncAttributeMaxDynamicSharedMemorySize, MOE_SMEM);

    zero_cnt_kernel<<<1, 32>>>();

    // --- self-attention ---
    gemm_nt<<<dim3(24, 64), 256, GEMM_SMEM>>>(x, sa_in_w, sa_in_b, nullptr, qkv,
                                              NTOK, 1536, 512);
    flash_attn<<<dim3(32, 16), 256, FLASH_SMEM>>>(qkv, 1536, qkv + 512, 1536,
                                                  qkv + 1024, 1536, attn, SEQ);
    gemm_nt<<<dim3(8, 64), 256, GEMM_SMEM>>>(attn, sa_out_w, sa_out_b, x, tmp,
                                             NTOK, 512, 512);
    layernorm_k<<<NTOK, 128>>>(tmp, ln1_g, ln1_b, x1);

    // --- cross-attention ---
    gemm_nt<<<dim3(8, 64), 256, GEMM_SMEM>>>(x1, ca_in_w, ca_in_b, nullptr, qkv,
                                             NTOK, 512, 512);
    gemm_nt<<<dim3(16, 64), 256, GEMM_SMEM>>>(memory, ca_in_w + 512 * 512,
                                              ca_in_b + 512, nullptr,
                                              qkv + (size_t)NTOK * 512, NTOK, 1024, 512);
    flash_attn<<<dim3(32, 16), 256, FLASH_SMEM>>>(qkv, 512,
                                                  qkv + (size_t)NTOK * 512, 1024,
                                                  qkv + (size_t)NTOK * 512 + 512, 1024,
                                                  attn, SEQ);
    gemm_nt<<<dim3(8, 64), 256, GEMM_SMEM>>>(attn, ca_out_w, ca_out_b, x1, tmp,
                                             NTOK, 512, 512);
    layernorm_k<<<NTOK, 128>>>(tmp, ln2_g, ln2_b, x2);

    // --- MoE FFN (top-1 routed) ---
    gate_k<<<NTOK / 8, 256>>>(x2, gate_w, gate_b);
    gemm_moe<true,  false><<<dim3(32, 256), 256, MOE_SMEM>>>(x2,   w1, b1, nullptr,
                                                             hbuf, 512, 2048);
    gemm_moe<false, true ><<<dim3(8,  256), 256, MOE_SMEM>>>(hbuf, w2, b2, x2,
                                                             tmp,  2048, 512);
    layernorm_k<<<NTOK, 128>>>(tmp, ln3_g, ln3_b, out);
}